// round 1
// baseline (speedup 1.0000x reference)
#include <cuda_runtime.h>
#include <stdint.h>

// Problem constants (fixed by setup_inputs)
#define NQ   6400
#define CAMS 6
#define LTOT 7979
#define CH   256
#define DFFN 1024

// ---------------- scratch (static device globals; no allocation) ----------------
__device__ float g_vproj[CAMS * LTOT * CH];   // 49 MB: value @ W_value + b
__device__ float g_off[NQ * CH];              // sampling offsets (pre-normalizer)
__device__ float g_aw[NQ * 128];              // attn logits -> softmax'd weights
__device__ float g_agg[NQ * CH];              // Sum over visible cams of sampled features
__device__ float g_proj[NQ * CH];             // agg @ W_out
__device__ float g_x[NQ * CH];                // after LN1
__device__ float g_ffn1[NQ * DFFN];           // relu(x@W1+b1)
__device__ float g_ffn2[NQ * CH];             // ffn1@W2+b2
__device__ unsigned int g_vis[NQ];            // per-query camera visibility bitmask
__device__ float g_cnt[NQ];                   // number of visible cameras (float)

__constant__ int c_W[4] = {100, 50, 25, 13};
__constant__ int c_H[4] = {60, 30, 15, 8};
__constant__ int c_S[4] = {0, 6000, 7500, 7875};

// ---------------- visibility mask ----------------
__global__ void mask_kernel(const int* __restrict__ bev) {
    int n = blockIdx.x * blockDim.x + threadIdx.x;
    if (n >= NQ) return;
    unsigned int vm = 0;
    int cnt = 0;
    #pragma unroll
    for (int k = 0; k < CAMS; k++) {
        const int* bp = bev + ((size_t)k * NQ + n) * 4;
        int s = bp[0] + bp[1] + bp[2] + bp[3];
        if (s > 0) { vm |= (1u << k); cnt++; }
    }
    g_vis[n] = vm;
    g_cnt[n] = (float)cnt;
}

// ---------------- tiled fp32 GEMM: C = A(MxK) * B(KxN) (+bias)(+relu) ----------------
// 128x64 tile, BK=16, 256 threads, 8x4 per-thread microtile.
// EPI: 0 = none, 1 = +bias, 2 = +bias then relu
template<int EPI>
__global__ __launch_bounds__(256) void sgemm_kernel(
    const float* __restrict__ A, const float* __restrict__ B,
    const float* __restrict__ bias, float* __restrict__ Cc,
    int M, int N, int K)
{
    __shared__ float As[16][128];
    __shared__ float Bs[16][64];
    const int tid = threadIdx.x;
    const int bm = blockIdx.x * 128;
    const int bn = blockIdx.y * 64;
    const int tx = tid & 15;   // -> 4 cols
    const int ty = tid >> 4;   // -> 8 rows

    float acc[8][4];
    #pragma unroll
    for (int i = 0; i < 8; i++)
        #pragma unroll
        for (int j = 0; j < 4; j++) acc[i][j] = 0.0f;

    // A tile: 128x16 = 512 float4, 2 per thread
    const int ar0 = tid >> 2;            // 0..63
    const int ac0 = (tid & 3) * 4;       // 0/4/8/12
    const int ar1 = ar0 + 64;
    // B tile: 16x64 = 256 float4, 1 per thread
    const int bkk = tid >> 4;            // 0..15
    const int bcn = (tid & 15) * 4;

    for (int k0 = 0; k0 < K; k0 += 16) {
        float4 av0 = make_float4(0.f, 0.f, 0.f, 0.f);
        float4 av1 = av0;
        int r0 = bm + ar0, r1 = bm + ar1;
        if (r0 < M) av0 = *(const float4*)(A + (size_t)r0 * K + k0 + ac0);
        if (r1 < M) av1 = *(const float4*)(A + (size_t)r1 * K + k0 + ac0);
        float4 bv = *(const float4*)(B + (size_t)(k0 + bkk) * N + bn + bcn);

        __syncthreads();
        As[ac0 + 0][ar0] = av0.x; As[ac0 + 1][ar0] = av0.y;
        As[ac0 + 2][ar0] = av0.z; As[ac0 + 3][ar0] = av0.w;
        As[ac0 + 0][ar1] = av1.x; As[ac0 + 1][ar1] = av1.y;
        As[ac0 + 2][ar1] = av1.z; As[ac0 + 3][ar1] = av1.w;
        *(float4*)&Bs[bkk][bcn] = bv;
        __syncthreads();

        #pragma unroll
        for (int kk = 0; kk < 16; kk++) {
            float4 b4 = *(const float4*)&Bs[kk][tx * 4];
            float4 a0 = *(const float4*)&As[kk][ty * 8];
            float4 a1 = *(const float4*)&As[kk][ty * 8 + 4];
            float a[8] = {a0.x, a0.y, a0.z, a0.w, a1.x, a1.y, a1.z, a1.w};
            float b[4] = {b4.x, b4.y, b4.z, b4.w};
            #pragma unroll
            for (int i = 0; i < 8; i++)
                #pragma unroll
                for (int j = 0; j < 4; j++)
                    acc[i][j] = fmaf(a[i], b[j], acc[i][j]);
        }
    }

    float4 bb = make_float4(0.f, 0.f, 0.f, 0.f);
    if (EPI >= 1) bb = *(const float4*)(bias + bn + tx * 4);
    #pragma unroll
    for (int i = 0; i < 8; i++) {
        int row = bm + ty * 8 + i;
        if (row >= M) continue;
        float4 o;
        o.x = acc[i][0] + bb.x;
        o.y = acc[i][1] + bb.y;
        o.z = acc[i][2] + bb.z;
        o.w = acc[i][3] + bb.w;
        if (EPI == 2) {
            o.x = fmaxf(o.x, 0.f); o.y = fmaxf(o.y, 0.f);
            o.z = fmaxf(o.z, 0.f); o.w = fmaxf(o.w, 0.f);
        }
        *(float4*)(Cc + (size_t)row * N + bn + tx * 4) = o;
    }
}

// ---------------- softmax over groups of 16 (per query, per head) ----------------
__global__ void softmax16_kernel(float* __restrict__ aw) {
    int g = blockIdx.x * blockDim.x + threadIdx.x;
    if (g >= NQ * 8) return;
    float* p = aw + (size_t)g * 16;
    float v[16];
    float mx = -1e30f;
    #pragma unroll
    for (int i = 0; i < 16; i++) { v[i] = p[i]; mx = fmaxf(mx, v[i]); }
    float s = 0.f;
    #pragma unroll
    for (int i = 0; i < 16; i++) { v[i] = expf(v[i] - mx); s += v[i]; }
    float inv = 1.0f / s;
    #pragma unroll
    for (int i = 0; i < 16; i++) p[i] = v[i] * inv;
}

// ---------------- deformable sampling + cross-camera aggregation ----------------
// One block per query. Phase 1: 768 (cam,head,lvl,pt) combos -> corner weights
// (aw folded in, OOB corners zero-weighted) + clamped corner coords in smem.
// Phase 2: thread c (=h*32+d) gathers 4 corners per combo, accumulates.
__global__ __launch_bounds__(256) void sample_kernel(
    const float* __restrict__ ref)   // (6, 6400, 4, 2)
{
    __shared__ float4 sw[768];
    __shared__ unsigned int sxy[768];
    const int n = blockIdx.x;
    const int tid = threadIdx.x;
    const unsigned int vism = g_vis[n];

    #pragma unroll
    for (int t = 0; t < 3; t++) {
        int cid = tid + t * 256;
        int k = cid >> 7;
        int r = cid & 127;          // h*16 + lvl*4 + p
        int h = r >> 4;
        int lvl = (r >> 2) & 3;
        int p = r & 3;
        float4 wv = make_float4(0.f, 0.f, 0.f, 0.f);
        unsigned int xy = 0;
        if ((vism >> k) & 1) {
            int Wi = c_W[lvl], Hi = c_H[lvl];
            float Wf = (float)Wi, Hf = (float)Hi;
            const float* rp = ref + (((size_t)k * NQ + n) * 4 + lvl) * 2;
            float rx = rp[0], ry = rp[1];
            int oi = ((h * 4 + lvl) * 4 + p) * 2;
            float ox = g_off[n * CH + oi];
            float oy = g_off[n * CH + oi + 1];
            float x = (rx + ox / Wf) * Wf - 0.5f;
            float y = (ry + oy / Hf) * Hf - 0.5f;
            float x0f = floorf(x), y0f = floorf(y);
            float lx = x - x0f, ly = y - y0f;
            int x0 = (int)x0f, y0 = (int)y0f;
            float a = g_aw[n * 128 + r];
            bool vx0 = (x0 >= 0) && (x0 < Wi);
            bool vx1 = (x0 + 1 >= 0) && (x0 + 1 < Wi);
            bool vy0 = (y0 >= 0) && (y0 < Hi);
            bool vy1 = (y0 + 1 >= 0) && (y0 + 1 < Hi);
            float omx = 1.0f - lx, omy = 1.0f - ly;
            wv.x = (vx0 && vy0) ? a * omx * omy : 0.0f;
            wv.y = (vx1 && vy0) ? a * lx * omy : 0.0f;
            wv.z = (vx0 && vy1) ? a * omx * ly : 0.0f;
            wv.w = (vx1 && vy1) ? a * lx * ly : 0.0f;
            int xc0 = min(max(x0, 0), Wi - 1);
            int xc1 = min(max(x0 + 1, 0), Wi - 1);
            int yc0 = min(max(y0, 0), Hi - 1);
            int yc1 = min(max(y0 + 1, 0), Hi - 1);
            xy = (unsigned)xc0 | ((unsigned)xc1 << 8) |
                 ((unsigned)yc0 << 16) | ((unsigned)yc1 << 24);
        }
        sw[cid] = wv;
        sxy[cid] = xy;
    }
    __syncthreads();

    const int h = tid >> 5;
    const int LW[4] = {100, 50, 25, 13};
    const int LS[4] = {0, 6000, 7500, 7875};
    float acc = 0.0f;
    #pragma unroll 1
    for (int k = 0; k < CAMS; k++) {
        if (!((vism >> k) & 1)) continue;
        const float* vb = g_vproj + (size_t)k * (LTOT * CH) + tid;
        const int base = k * 128 + h * 16;
        #pragma unroll
        for (int i = 0; i < 16; i++) {
            float4 w = sw[base + i];
            unsigned int xy = sxy[base + i];
            const int lvl = i >> 2;
            const int Ws = LW[lvl], Ss = LS[lvl];
            int xc0 = xy & 255, xc1 = (xy >> 8) & 255;
            int yc0 = (xy >> 16) & 255, yc1 = xy >> 24;
            int r0 = (Ss + yc0 * Ws) << 8;
            int r1 = (Ss + yc1 * Ws) << 8;
            acc = fmaf(w.x, vb[r0 + (xc0 << 8)], acc);
            acc = fmaf(w.y, vb[r0 + (xc1 << 8)], acc);
            acc = fmaf(w.z, vb[r1 + (xc0 << 8)], acc);
            acc = fmaf(w.w, vb[r1 + (xc1 << 8)], acc);
        }
    }
    g_agg[(size_t)n * CH + tid] = acc;
}

// ---------------- block reduction helper ----------------
__device__ __forceinline__ float blocksum256(float v, float* sh) {
    #pragma unroll
    for (int o = 16; o > 0; o >>= 1) v += __shfl_xor_sync(0xffffffffu, v, o);
    if ((threadIdx.x & 31) == 0) sh[threadIdx.x >> 5] = v;
    __syncthreads();
    float s = 0.f;
    #pragma unroll
    for (int i = 0; i < 8; i++) s += sh[i];
    __syncthreads();
    return s;
}

// ---------------- slots assembly + residual + LN1 ----------------
__global__ __launch_bounds__(256) void ln1_kernel(
    const float* __restrict__ query, const float* __restrict__ b_out,
    const float* __restrict__ gamma, const float* __restrict__ beta)
{
    __shared__ float sh[8];
    const int n = blockIdx.x, c = threadIdx.x;
    float m = g_cnt[n];
    float q = query[(size_t)n * CH + c];
    float s = m * (q + b_out[c]) + g_proj[(size_t)n * CH + c];
    float t = s / fmaxf(m, 1.0f) + q;
    float mu = blocksum256(t, sh) * (1.0f / CH);
    float d = t - mu;
    float var = blocksum256(d * d, sh) * (1.0f / CH);
    g_x[(size_t)n * CH + c] = d * rsqrtf(var + 1e-5f) * gamma[c] + beta[c];
}

// ---------------- FFN residual + LN2 -> output ----------------
__global__ __launch_bounds__(256) void ln2_kernel(
    const float* __restrict__ gamma, const float* __restrict__ beta,
    float* __restrict__ out)
{
    __shared__ float sh[8];
    const int n = blockIdx.x, c = threadIdx.x;
    float t = g_x[(size_t)n * CH + c] + g_ffn2[(size_t)n * CH + c];
    float mu = blocksum256(t, sh) * (1.0f / CH);
    float d = t - mu;
    float var = blocksum256(d * d, sh) * (1.0f / CH);
    out[(size_t)n * CH + c] = d * rsqrtf(var + 1e-5f) * gamma[c] + beta[c];
}

// ---------------- host launcher ----------------
extern "C" void kernel_launch(void* const* d_in, const int* in_sizes, int n_in,
                              void* d_out, int out_size) {
    const float* query   = (const float*)d_in[0];
    // d_in[1] = key (unused by reference)
    const float* value   = (const float*)d_in[2];
    const float* refpts  = (const float*)d_in[3];
    // d_in[4] spatial_shapes, d_in[5] level_start_index: compile-time constants
    const int*   bev     = (const int*)d_in[6];
    const float* W_value = (const float*)d_in[7];
    const float* b_value = (const float*)d_in[8];
    const float* W_off   = (const float*)d_in[9];
    const float* b_off   = (const float*)d_in[10];
    const float* W_attn  = (const float*)d_in[11];
    const float* b_attn  = (const float*)d_in[12];
    const float* W_out   = (const float*)d_in[13];
    const float* b_out   = (const float*)d_in[14];
    const float* ln1_g   = (const float*)d_in[15];
    const float* ln1_b   = (const float*)d_in[16];
    const float* W1      = (const float*)d_in[17];
    const float* b1      = (const float*)d_in[18];
    const float* W2      = (const float*)d_in[19];
    const float* b2      = (const float*)d_in[20];
    const float* ln2_g   = (const float*)d_in[21];
    const float* ln2_b   = (const float*)d_in[22];
    float* out = (float*)d_out;

    // Scratch addresses (host-side symbol queries; no stream ops, no allocation)
    void *p_vproj, *p_off, *p_aw, *p_agg, *p_proj, *p_x, *p_ffn1, *p_ffn2;
    cudaGetSymbolAddress(&p_vproj, g_vproj);
    cudaGetSymbolAddress(&p_off,   g_off);
    cudaGetSymbolAddress(&p_aw,    g_aw);
    cudaGetSymbolAddress(&p_agg,   g_agg);
    cudaGetSymbolAddress(&p_proj,  g_proj);
    cudaGetSymbolAddress(&p_x,     g_x);
    cudaGetSymbolAddress(&p_ffn1,  g_ffn1);
    cudaGetSymbolAddress(&p_ffn2,  g_ffn2);

    // 1. visibility mask + counts
    mask_kernel<<<(NQ + 255) / 256, 256>>>(bev);

    // 2. value projection: (6*7979, 256) @ (256, 256) + b_value
    {
        dim3 grid((CAMS * LTOT + 127) / 128, CH / 64);
        sgemm_kernel<1><<<grid, 256>>>(value, W_value, b_value,
                                       (float*)p_vproj, CAMS * LTOT, CH, CH);
    }
    // 3. sampling offsets: (6400, 256) @ (256, 256) + b_off
    {
        dim3 grid((NQ + 127) / 128, CH / 64);
        sgemm_kernel<1><<<grid, 256>>>(query, W_off, b_off,
                                       (float*)p_off, NQ, CH, CH);
    }
    // 4. attention logits: (6400, 256) @ (256, 128) + b_attn
    {
        dim3 grid((NQ + 127) / 128, 128 / 64);
        sgemm_kernel<1><<<grid, 256>>>(query, W_attn, b_attn,
                                       (float*)p_aw, NQ, 128, CH);
    }
    // 5. softmax over 16 points per (query, head)
    softmax16_kernel<<<(NQ * 8 + 255) / 256, 256>>>((float*)p_aw);

    // 6. bilinear sampling + cross-camera aggregation
    sample_kernel<<<NQ, 256>>>(refpts);

    // 7. output projection: agg @ W_out (bias folded into ln1)
    {
        dim3 grid((NQ + 127) / 128, CH / 64);
        sgemm_kernel<0><<<grid, 256>>>((const float*)p_agg, W_out, nullptr,
                                       (float*)p_proj, NQ, CH, CH);
    }
    // 8. slots + residual + LN1
    ln1_kernel<<<NQ, 256>>>(query, b_out, ln1_g, ln1_b);

    // 9. FFN up: relu(x @ W1 + b1)
    {
        dim3 grid((NQ + 127) / 128, DFFN / 64);
        sgemm_kernel<2><<<grid, 256>>>((const float*)p_x, W1, b1,
                                       (float*)p_ffn1, NQ, DFFN, CH);
    }
    // 10. FFN down: ffn1 @ W2 + b2
    {
        dim3 grid((NQ + 127) / 128, CH / 64);
        sgemm_kernel<1><<<grid, 256>>>((const float*)p_ffn1, W2, b2,
                                       (float*)p_ffn2, NQ, CH, DFFN);
    }
    // 11. residual + LN2 -> out
    ln2_kernel<<<NQ, 256>>>(ln2_g, ln2_b, out);

    (void)in_sizes; (void)n_in; (void)out_size;
}

// round 2
// speedup vs baseline: 1.6682x; 1.6682x over previous
#include <cuda_runtime.h>
#include <cuda_bf16.h>
#include <stdint.h>

// Problem constants (fixed by setup_inputs)
#define NQ   6400
#define CAMS 6
#define LTOT 7979
#define CH   256
#define DFFN 1024

// ---------------- scratch (static device globals; no allocation) ----------------
__device__ __nv_bfloat16 g_vproj[CAMS * LTOT * CH]; // 24.5 MB: value @ W_value + b (bf16)
__device__ float g_off[NQ * CH];              // sampling offsets
__device__ float g_aw[NQ * 128];              // attn logits -> softmax'd weights
__device__ float g_agg[NQ * CH];              // Sum over visible cams of sampled features
__device__ float g_proj[NQ * CH];             // agg @ W_out
__device__ float g_x[NQ * CH];                // after LN1
__device__ float g_ffn1[NQ * DFFN];           // relu(x@W1+b1)
__device__ float g_ffn2[NQ * CH];             // ffn1@W2+b2
__device__ unsigned int g_vis[NQ];            // per-query camera visibility bitmask
__device__ float g_cnt[NQ];                   // number of visible cameras (float)

__constant__ int c_W[4] = {100, 50, 25, 13};
__constant__ int c_H[4] = {60, 30, 15, 8};

// ---------------- visibility mask ----------------
__global__ void mask_kernel(const int* __restrict__ bev) {
    int n = blockIdx.x * blockDim.x + threadIdx.x;
    if (n >= NQ) return;
    unsigned int vm = 0;
    int cnt = 0;
    #pragma unroll
    for (int k = 0; k < CAMS; k++) {
        const int* bp = bev + ((size_t)k * NQ + n) * 4;
        int s = bp[0] + bp[1] + bp[2] + bp[3];
        if (s > 0) { vm |= (1u << k); cnt++; }
    }
    g_vis[n] = vm;
    g_cnt[n] = (float)cnt;
}

// ---------------- tensor-core GEMM building blocks ----------------
__device__ __forceinline__ void ldsm4(uint32_t* r, const void* p) {
    uint32_t a = (uint32_t)__cvta_generic_to_shared(p);
    asm volatile("ldmatrix.sync.aligned.m8n8.x4.shared.b16 {%0,%1,%2,%3}, [%4];"
                 : "=r"(r[0]), "=r"(r[1]), "=r"(r[2]), "=r"(r[3]) : "r"(a));
}

__device__ __forceinline__ void mma_bf16(float* d, const uint32_t* a, const uint32_t* b) {
    asm volatile("mma.sync.aligned.m16n8k16.row.col.f32.bf16.bf16.f32 "
                 "{%0,%1,%2,%3}, {%4,%5,%6,%7}, {%8,%9}, {%0,%1,%2,%3};"
                 : "+f"(d[0]), "+f"(d[1]), "+f"(d[2]), "+f"(d[3])
                 : "r"(a[0]), "r"(a[1]), "r"(a[2]), "r"(a[3]), "r"(b[0]), "r"(b[1]));
}

__device__ __forceinline__ void store2(float* C, float x, float y) {
    *(float2*)C = make_float2(x, y);
}
__device__ __forceinline__ void store2(__nv_bfloat16* C, float x, float y) {
    *(__nv_bfloat162*)C = __floats2bfloat162_rn(x, y);
}

// ---------------- bf16 tensor-core GEMM: C = A(MxK,f32) * B(KxN,f32) (+bias)(+relu) ----
// Block tile 128(m) x 64(n), BK=32, 256 threads (8 warps, each 32x32).
// A,B loaded fp32 from gmem, converted to bf16 on the smem store. fp32 accumulate.
// EPI: 0 = none, 1 = +bias, 2 = +bias then relu. OutT: float or __nv_bfloat16.
template<int EPI, typename OutT>
__global__ __launch_bounds__(256, 2) void hgemm_kernel(
    const float* __restrict__ A, const float* __restrict__ B,
    const float* __restrict__ bias, OutT* __restrict__ C,
    int M, int N, int K)
{
    __shared__ __align__(16) __nv_bfloat16 As[128][40];  // 40-elem (80B) pad: LDSM conflict-free
    __shared__ __align__(16) __nv_bfloat16 Bs[64][40];   // stored [n][k]
    const int tid = threadIdx.x;
    const int bm = blockIdx.x * 128, bn = blockIdx.y * 64;
    const int lane = tid & 31, w = tid >> 5;
    const int m0 = (w >> 1) * 32, n0 = (w & 1) * 32;

    float acc[2][4][4];
    #pragma unroll
    for (int i = 0; i < 2; i++)
        #pragma unroll
        for (int j = 0; j < 4; j++)
            #pragma unroll
            for (int l = 0; l < 4; l++) acc[i][j][l] = 0.0f;

    const int arow = tid >> 3, acol = (tid & 7) * 4;   // A: 32 rows per pass, 4 cols
    const int bk = tid >> 4, bn4 = (tid & 15) * 4;     // B: 16 k per pass, 4 n

    float4 ar[4], br[2];

    // prefetch k0 = 0
    #pragma unroll
    for (int p = 0; p < 4; p++) {
        int r = bm + arow + p * 32; r = r < M ? r : M - 1;
        ar[p] = *(const float4*)(A + (size_t)r * K + acol);
    }
    #pragma unroll
    for (int p = 0; p < 2; p++)
        br[p] = *(const float4*)(B + (size_t)(bk + p * 16) * N + bn + bn4);

    for (int k0 = 0; k0 < K; k0 += 32) {
        __syncthreads();
        // store tiles (fp32 -> bf16)
        #pragma unroll
        for (int p = 0; p < 4; p++) {
            int row = arow + p * 32;
            *(__nv_bfloat162*)&As[row][acol]     = __floats2bfloat162_rn(ar[p].x, ar[p].y);
            *(__nv_bfloat162*)&As[row][acol + 2] = __floats2bfloat162_rn(ar[p].z, ar[p].w);
        }
        #pragma unroll
        for (int p = 0; p < 2; p++) {
            int kk = bk + p * 16;
            Bs[bn4 + 0][kk] = __float2bfloat16_rn(br[p].x);
            Bs[bn4 + 1][kk] = __float2bfloat16_rn(br[p].y);
            Bs[bn4 + 2][kk] = __float2bfloat16_rn(br[p].z);
            Bs[bn4 + 3][kk] = __float2bfloat16_rn(br[p].w);
        }
        __syncthreads();

        // prefetch next k tile while computing this one
        if (k0 + 32 < K) {
            #pragma unroll
            for (int p = 0; p < 4; p++) {
                int r = bm + arow + p * 32; r = r < M ? r : M - 1;
                ar[p] = *(const float4*)(A + (size_t)r * K + k0 + 32 + acol);
            }
            #pragma unroll
            for (int p = 0; p < 2; p++)
                br[p] = *(const float4*)(B + (size_t)(k0 + 32 + bk + p * 16) * N + bn + bn4);
        }

        #pragma unroll
        for (int ks = 0; ks < 2; ks++) {
            uint32_t af[2][4], bfr[4][2];
            #pragma unroll
            for (int mt = 0; mt < 2; mt++)
                ldsm4(af[mt], &As[m0 + mt * 16 + (lane & 15)][ks * 16 + ((lane >> 4) << 3)]);
            #pragma unroll
            for (int nt2 = 0; nt2 < 2; nt2++) {
                uint32_t t[4];
                ldsm4(t, &Bs[n0 + nt2 * 16 + (lane & 15)][ks * 16 + ((lane >> 4) << 3)]);
                bfr[nt2 * 2][0] = t[0];  bfr[nt2 * 2][1] = t[2];
                bfr[nt2 * 2 + 1][0] = t[1];  bfr[nt2 * 2 + 1][1] = t[3];
            }
            #pragma unroll
            for (int mt = 0; mt < 2; mt++)
                #pragma unroll
                for (int nt = 0; nt < 4; nt++)
                    mma_bf16(acc[mt][nt], af[mt], bfr[nt]);
        }
    }

    // epilogue
    const int row0 = bm + m0 + (lane >> 2);
    #pragma unroll
    for (int mt = 0; mt < 2; mt++) {
        int r0 = row0 + mt * 16, r1 = r0 + 8;
        #pragma unroll
        for (int nt = 0; nt < 4; nt++) {
            int col = bn + n0 + nt * 8 + ((lane & 3) << 1);
            float b0 = 0.f, b1 = 0.f;
            if (EPI >= 1) { b0 = __ldg(bias + col); b1 = __ldg(bias + col + 1); }
            float v0 = acc[mt][nt][0] + b0, v1 = acc[mt][nt][1] + b1;
            float v2 = acc[mt][nt][2] + b0, v3 = acc[mt][nt][3] + b1;
            if (EPI == 2) {
                v0 = fmaxf(v0, 0.f); v1 = fmaxf(v1, 0.f);
                v2 = fmaxf(v2, 0.f); v3 = fmaxf(v3, 0.f);
            }
            if (r0 < M) store2(C + (size_t)r0 * N + col, v0, v1);
            if (r1 < M) store2(C + (size_t)r1 * N + col, v2, v3);
        }
    }
}

// ---------------- softmax over groups of 16 (per query, per head) ----------------
__global__ void softmax16_kernel(float* __restrict__ aw) {
    int g = blockIdx.x * blockDim.x + threadIdx.x;
    if (g >= NQ * 8) return;
    float* p = aw + (size_t)g * 16;
    float v[16];
    float mx = -1e30f;
    #pragma unroll
    for (int i = 0; i < 16; i++) { v[i] = p[i]; mx = fmaxf(mx, v[i]); }
    float s = 0.f;
    #pragma unroll
    for (int i = 0; i < 16; i++) { v[i] = expf(v[i] - mx); s += v[i]; }
    float inv = 1.0f / s;
    #pragma unroll
    for (int i = 0; i < 16; i++) p[i] = v[i] * inv;
}

// ---------------- deformable sampling + cross-camera aggregation ----------------
__global__ __launch_bounds__(256) void sample_kernel(
    const float* __restrict__ ref)   // (6, 6400, 4, 2)
{
    __shared__ float4 sw[768];
    __shared__ unsigned int sxy[768];
    const int n = blockIdx.x;
    const int tid = threadIdx.x;
    const unsigned int vism = g_vis[n];

    #pragma unroll
    for (int t = 0; t < 3; t++) {
        int cid = tid + t * 256;
        int k = cid >> 7;
        int r = cid & 127;          // h*16 + lvl*4 + p
        int h = r >> 4;
        int lvl = (r >> 2) & 3;
        int p = r & 3;
        float4 wv = make_float4(0.f, 0.f, 0.f, 0.f);
        unsigned int xy = 0;
        if ((vism >> k) & 1) {
            int Wi = c_W[lvl], Hi = c_H[lvl];
            float Wf = (float)Wi, Hf = (float)Hi;
            const float* rp = ref + (((size_t)k * NQ + n) * 4 + lvl) * 2;
            float rx = rp[0], ry = rp[1];
            int oi = ((h * 4 + lvl) * 4 + p) * 2;
            float ox = g_off[n * CH + oi];
            float oy = g_off[n * CH + oi + 1];
            float x = (rx + ox / Wf) * Wf - 0.5f;
            float y = (ry + oy / Hf) * Hf - 0.5f;
            float x0f = floorf(x), y0f = floorf(y);
            float lx = x - x0f, ly = y - y0f;
            int x0 = (int)x0f, y0 = (int)y0f;
            float a = g_aw[n * 128 + r];
            bool vx0 = (x0 >= 0) && (x0 < Wi);
            bool vx1 = (x0 + 1 >= 0) && (x0 + 1 < Wi);
            bool vy0 = (y0 >= 0) && (y0 < Hi);
            bool vy1 = (y0 + 1 >= 0) && (y0 + 1 < Hi);
            float omx = 1.0f - lx, omy = 1.0f - ly;
            wv.x = (vx0 && vy0) ? a * omx * omy : 0.0f;
            wv.y = (vx1 && vy0) ? a * lx * omy : 0.0f;
            wv.z = (vx0 && vy1) ? a * omx * ly : 0.0f;
            wv.w = (vx1 && vy1) ? a * lx * ly : 0.0f;
            int xc0 = min(max(x0, 0), Wi - 1);
            int xc1 = min(max(x0 + 1, 0), Wi - 1);
            int yc0 = min(max(y0, 0), Hi - 1);
            int yc1 = min(max(y0 + 1, 0), Hi - 1);
            xy = (unsigned)xc0 | ((unsigned)xc1 << 8) |
                 ((unsigned)yc0 << 16) | ((unsigned)yc1 << 24);
        }
        sw[cid] = wv;
        sxy[cid] = xy;
    }
    __syncthreads();

    const int h = tid >> 5;
    const int LW[4] = {100, 50, 25, 13};
    const int LS[4] = {0, 6000, 7500, 7875};
    float acc = 0.0f;
    #pragma unroll 1
    for (int k = 0; k < CAMS; k++) {
        if (!((vism >> k) & 1)) continue;
        const __nv_bfloat16* vb = g_vproj + (size_t)k * (LTOT * CH) + tid;
        const int base = k * 128 + h * 16;
        #pragma unroll
        for (int i = 0; i < 16; i++) {
            float4 w = sw[base + i];
            unsigned int xy = sxy[base + i];
            const int lvl = i >> 2;
            const int Ws = LW[lvl], Ss = LS[lvl];
            int xc0 = xy & 255, xc1 = (xy >> 8) & 255;
            int yc0 = (xy >> 16) & 255, yc1 = xy >> 24;
            int r0 = (Ss + yc0 * Ws) << 8;
            int r1 = (Ss + yc1 * Ws) << 8;
            acc = fmaf(w.x, __bfloat162float(vb[r0 + (xc0 << 8)]), acc);
            acc = fmaf(w.y, __bfloat162float(vb[r0 + (xc1 << 8)]), acc);
            acc = fmaf(w.z, __bfloat162float(vb[r1 + (xc0 << 8)]), acc);
            acc = fmaf(w.w, __bfloat162float(vb[r1 + (xc1 << 8)]), acc);
        }
    }
    g_agg[(size_t)n * CH + tid] = acc;
}

// ---------------- block reduction helper ----------------
__device__ __forceinline__ float blocksum256(float v, float* sh) {
    #pragma unroll
    for (int o = 16; o > 0; o >>= 1) v += __shfl_xor_sync(0xffffffffu, v, o);
    if ((threadIdx.x & 31) == 0) sh[threadIdx.x >> 5] = v;
    __syncthreads();
    float s = 0.f;
    #pragma unroll
    for (int i = 0; i < 8; i++) s += sh[i];
    __syncthreads();
    return s;
}

// ---------------- slots assembly + residual + LN1 ----------------
__global__ __launch_bounds__(256) void ln1_kernel(
    const float* __restrict__ query, const float* __restrict__ b_out,
    const float* __restrict__ gamma, const float* __restrict__ beta)
{
    __shared__ float sh[8];
    const int n = blockIdx.x, c = threadIdx.x;
    float m = g_cnt[n];
    float q = query[(size_t)n * CH + c];
    float s = m * (q + b_out[c]) + g_proj[(size_t)n * CH + c];
    float t = s / fmaxf(m, 1.0f) + q;
    float mu = blocksum256(t, sh) * (1.0f / CH);
    float d = t - mu;
    float var = blocksum256(d * d, sh) * (1.0f / CH);
    g_x[(size_t)n * CH + c] = d * rsqrtf(var + 1e-5f) * gamma[c] + beta[c];
}

// ---------------- FFN residual + LN2 -> output ----------------
__global__ __launch_bounds__(256) void ln2_kernel(
    const float* __restrict__ gamma, const float* __restrict__ beta,
    float* __restrict__ out)
{
    __shared__ float sh[8];
    const int n = blockIdx.x, c = threadIdx.x;
    float t = g_x[(size_t)n * CH + c] + g_ffn2[(size_t)n * CH + c];
    float mu = blocksum256(t, sh) * (1.0f / CH);
    float d = t - mu;
    float var = blocksum256(d * d, sh) * (1.0f / CH);
    out[(size_t)n * CH + c] = d * rsqrtf(var + 1e-5f) * gamma[c] + beta[c];
}

// ---------------- host launcher ----------------
extern "C" void kernel_launch(void* const* d_in, const int* in_sizes, int n_in,
                              void* d_out, int out_size) {
    const float* query   = (const float*)d_in[0];
    // d_in[1] = key (unused by reference)
    const float* value   = (const float*)d_in[2];
    const float* refpts  = (const float*)d_in[3];
    // d_in[4] spatial_shapes, d_in[5] level_start_index: compile-time constants
    const int*   bev     = (const int*)d_in[6];
    const float* W_value = (const float*)d_in[7];
    const float* b_value = (const float*)d_in[8];
    const float* W_off   = (const float*)d_in[9];
    const float* b_off   = (const float*)d_in[10];
    const float* W_attn  = (const float*)d_in[11];
    const float* b_attn  = (const float*)d_in[12];
    const float* W_out   = (const float*)d_in[13];
    const float* b_out   = (const float*)d_in[14];
    const float* ln1_g   = (const float*)d_in[15];
    const float* ln1_b   = (const float*)d_in[16];
    const float* W1      = (const float*)d_in[17];
    const float* b1      = (const float*)d_in[18];
    const float* W2      = (const float*)d_in[19];
    const float* b2      = (const float*)d_in[20];
    const float* ln2_g   = (const float*)d_in[21];
    const float* ln2_b   = (const float*)d_in[22];
    float* out = (float*)d_out;

    void *p_vproj, *p_off, *p_aw, *p_agg, *p_proj, *p_x, *p_ffn1, *p_ffn2;
    cudaGetSymbolAddress(&p_vproj, g_vproj);
    cudaGetSymbolAddress(&p_off,   g_off);
    cudaGetSymbolAddress(&p_aw,    g_aw);
    cudaGetSymbolAddress(&p_agg,   g_agg);
    cudaGetSymbolAddress(&p_proj,  g_proj);
    cudaGetSymbolAddress(&p_x,     g_x);
    cudaGetSymbolAddress(&p_ffn1,  g_ffn1);
    cudaGetSymbolAddress(&p_ffn2,  g_ffn2);

    // 1. visibility mask + counts
    mask_kernel<<<(NQ + 255) / 256, 256>>>(bev);

    // 2. value projection: (6*7979, 256) @ (256, 256) + b_value -> bf16
    hgemm_kernel<1, __nv_bfloat16><<<dim3((CAMS * LTOT + 127) / 128, CH / 64), 256>>>(
        value, W_value, b_value, (__nv_bfloat16*)p_vproj, CAMS * LTOT, CH, CH);

    // 3. sampling offsets: (6400, 256) @ (256, 256) + b_off
    hgemm_kernel<1, float><<<dim3(NQ / 128, CH / 64), 256>>>(
        query, W_off, b_off, (float*)p_off, NQ, CH, CH);

    // 4. attention logits: (6400, 256) @ (256, 128) + b_attn
    hgemm_kernel<1, float><<<dim3(NQ / 128, 128 / 64), 256>>>(
        query, W_attn, b_attn, (float*)p_aw, NQ, 128, CH);

    // 5. softmax over 16 points per (query, head)
    softmax16_kernel<<<(NQ * 8 + 255) / 256, 256>>>((float*)p_aw);

    // 6. bilinear sampling + cross-camera aggregation
    sample_kernel<<<NQ, 256>>>(refpts);

    // 7. output projection: agg @ W_out (bias folded into ln1)
    hgemm_kernel<0, float><<<dim3(NQ / 128, CH / 64), 256>>>(
        (const float*)p_agg, W_out, nullptr, (float*)p_proj, NQ, CH, CH);

    // 8. slots + residual + LN1
    ln1_kernel<<<NQ, 256>>>(query, b_out, ln1_g, ln1_b);

    // 9. FFN up: relu(x @ W1 + b1)
    hgemm_kernel<2, float><<<dim3(NQ / 128, DFFN / 64), 256>>>(
        (const float*)p_x, W1, b1, (float*)p_ffn1, NQ, DFFN, CH);

    // 10. FFN down: ffn1 @ W2 + b2
    hgemm_kernel<1, float><<<dim3(NQ / 128, CH / 64), 256>>>(
        (const float*)p_ffn1, W2, b2, (float*)p_ffn2, NQ, CH, DFFN);

    // 11. residual + LN2 -> out
    ln2_kernel<<<NQ, 256>>>(ln2_g, ln2_b, out);

    (void)in_sizes; (void)n_in; (void)out_size;
}

// round 3
// speedup vs baseline: 2.2335x; 1.3389x over previous
#include <cuda_runtime.h>
#include <cuda_bf16.h>
#include <stdint.h>

// Problem constants (fixed by setup_inputs)
#define NQ   6400
#define CAMS 6
#define LTOT 7979
#define CH   256
#define DFFN 1024

// ---------------- scratch (static device globals; no allocation) ----------------
__device__ __nv_bfloat16 g_vproj[CAMS * LTOT * CH]; // 24.5 MB: value @ W_value + b (bf16)
__device__ float g_off[NQ * CH];              // sampling offsets
__device__ float g_aw[NQ * 128];              // attn logits -> softmax'd weights
__device__ float g_agg[NQ * CH];              // Sum over visible cams of sampled features
__device__ float g_proj[NQ * CH];             // agg @ W_out
__device__ float g_x[NQ * CH];                // after LN1
__device__ float g_ffn1[NQ * DFFN];           // relu(x@W1+b1)
__device__ float g_ffn2[NQ * CH];             // ffn1@W2+b2
__device__ unsigned int g_vis[NQ];            // per-query camera visibility bitmask
__device__ float g_cnt[NQ];                   // number of visible cameras (float)

__constant__ int c_W[4] = {100, 50, 25, 13};
__constant__ int c_H[4] = {60, 30, 15, 8};

// ---------------- visibility mask ----------------
__global__ void mask_kernel(const int* __restrict__ bev) {
    int n = blockIdx.x * blockDim.x + threadIdx.x;
    if (n >= NQ) return;
    unsigned int vm = 0;
    int cnt = 0;
    #pragma unroll
    for (int k = 0; k < CAMS; k++) {
        const int* bp = bev + ((size_t)k * NQ + n) * 4;
        int s = bp[0] + bp[1] + bp[2] + bp[3];
        if (s > 0) { vm |= (1u << k); cnt++; }
    }
    g_vis[n] = vm;
    g_cnt[n] = (float)cnt;
}

// ---------------- tensor-core GEMM building blocks ----------------
__device__ __forceinline__ void ldsm4(uint32_t* r, const void* p) {
    uint32_t a = (uint32_t)__cvta_generic_to_shared(p);
    asm volatile("ldmatrix.sync.aligned.m8n8.x4.shared.b16 {%0,%1,%2,%3}, [%4];"
                 : "=r"(r[0]), "=r"(r[1]), "=r"(r[2]), "=r"(r[3]) : "r"(a));
}

__device__ __forceinline__ void mma_bf16(float* d, const uint32_t* a, const uint32_t* b) {
    asm volatile("mma.sync.aligned.m16n8k16.row.col.f32.bf16.bf16.f32 "
                 "{%0,%1,%2,%3}, {%4,%5,%6,%7}, {%8,%9}, {%0,%1,%2,%3};"
                 : "+f"(d[0]), "+f"(d[1]), "+f"(d[2]), "+f"(d[3])
                 : "r"(a[0]), "r"(a[1]), "r"(a[2]), "r"(a[3]), "r"(b[0]), "r"(b[1]));
}

__device__ __forceinline__ void store2(float* C, float x, float y) {
    *(float2*)C = make_float2(x, y);
}
__device__ __forceinline__ void store2(__nv_bfloat16* C, float x, float y) {
    *(__nv_bfloat162*)C = __floats2bfloat162_rn(x, y);
}

// ---------------- bf16 tensor-core GEMM, pipelined ----------------------------
// C = A(MxK,f32) * B(KxN,f32) (+bias)(+relu). Block tile 128x64, BK=32,
// 256 threads (8 warps x 32x32). Double-buffered smem (1 sync per k-tile) +
// 2-deep register prefetch => 3 k-tiles in flight.
// EPI: 0 none, 1 +bias, 2 +bias+relu.
template<int EPI, typename OutT>
__global__ __launch_bounds__(256, 2) void hgemm_kernel(
    const float* __restrict__ A, const float* __restrict__ B,
    const float* __restrict__ bias, OutT* __restrict__ C,
    int M, int N, int K)
{
    __shared__ __align__(16) __nv_bfloat16 As[2][128][40];  // pad 40 -> LDSM conflict-free
    __shared__ __align__(16) __nv_bfloat16 Bs[2][64][40];   // stored [n][k]
    const int tid = threadIdx.x;
    const int bm = blockIdx.x * 128, bn = blockIdx.y * 64;
    const int lane = tid & 31, w = tid >> 5;
    const int m0 = (w >> 1) * 32, n0 = (w & 1) * 32;

    float acc[2][4][4];
    #pragma unroll
    for (int i = 0; i < 2; i++)
        #pragma unroll
        for (int j = 0; j < 4; j++)
            #pragma unroll
            for (int l = 0; l < 4; l++) acc[i][j][l] = 0.0f;

    const int arow = tid >> 3, acol = (tid & 7) * 4;   // A: 4x (32 rows x 32 cols)
    const int bk = tid >> 4, bn4 = (tid & 15) * 4;     // B: 2x (16 k x 64 n)

    const float* Ap[4];
    #pragma unroll
    for (int p = 0; p < 4; p++) {
        int r = bm + arow + p * 32; r = r < M ? r : M - 1;
        Ap[p] = A + (size_t)r * K + acol;
    }
    const float* Bp0 = B + (size_t)bk * N + bn + bn4;
    const float* Bp1 = Bp0 + (size_t)16 * N;

    float4 arg[2][4];
    float4 brg[2][2];

#define G2R(s, k0) do {                                                        \
    _Pragma("unroll")                                                          \
    for (int p = 0; p < 4; p++) arg[s][p] = *(const float4*)(Ap[p] + (k0));    \
    brg[s][0] = *(const float4*)(Bp0 + (size_t)(k0) * N);                      \
    brg[s][1] = *(const float4*)(Bp1 + (size_t)(k0) * N);                      \
} while (0)

#define R2S(s, b) do {                                                         \
    _Pragma("unroll")                                                          \
    for (int p = 0; p < 4; p++) {                                              \
        int row = arow + p * 32;                                               \
        *(__nv_bfloat162*)&As[b][row][acol] =                                  \
            __floats2bfloat162_rn(arg[s][p].x, arg[s][p].y);                   \
        *(__nv_bfloat162*)&As[b][row][acol + 2] =                              \
            __floats2bfloat162_rn(arg[s][p].z, arg[s][p].w);                   \
    }                                                                          \
    _Pragma("unroll")                                                          \
    for (int p = 0; p < 2; p++) {                                              \
        int kk = bk + p * 16;                                                  \
        Bs[b][bn4 + 0][kk] = __float2bfloat16_rn(brg[s][p].x);                 \
        Bs[b][bn4 + 1][kk] = __float2bfloat16_rn(brg[s][p].y);                 \
        Bs[b][bn4 + 2][kk] = __float2bfloat16_rn(brg[s][p].z);                 \
        Bs[b][bn4 + 3][kk] = __float2bfloat16_rn(brg[s][p].w);                 \
    }                                                                          \
} while (0)

#define COMPUTE(b) do {                                                        \
    _Pragma("unroll")                                                          \
    for (int ks = 0; ks < 2; ks++) {                                           \
        uint32_t af[2][4], bfr[4][2];                                          \
        _Pragma("unroll")                                                      \
        for (int mt = 0; mt < 2; mt++)                                         \
            ldsm4(af[mt], &As[b][m0 + mt * 16 + (lane & 15)]                   \
                             [ks * 16 + ((lane >> 4) << 3)]);                  \
        _Pragma("unroll")                                                      \
        for (int nt2 = 0; nt2 < 2; nt2++) {                                    \
            uint32_t t[4];                                                     \
            ldsm4(t, &Bs[b][n0 + nt2 * 16 + (lane & 15)]                       \
                           [ks * 16 + ((lane >> 4) << 3)]);                    \
            bfr[nt2 * 2][0] = t[0];      bfr[nt2 * 2][1] = t[2];               \
            bfr[nt2 * 2 + 1][0] = t[1];  bfr[nt2 * 2 + 1][1] = t[3];           \
        }                                                                      \
        _Pragma("unroll")                                                      \
        for (int mt = 0; mt < 2; mt++)                                         \
            _Pragma("unroll")                                                  \
            for (int nt = 0; nt < 4; nt++)                                     \
                mma_bf16(acc[mt][nt], af[mt], bfr[nt]);                        \
    }                                                                          \
} while (0)

    const int KT = K >> 5;   // K is 256 or 1024 -> KT even
    G2R(0, 0);
    R2S(0, 0);
    G2R(1, 32);
    __syncthreads();

    for (int kt = 0; kt < KT; kt += 2) {
        if (kt + 2 < KT) G2R(0, (kt + 2) * 32);
        COMPUTE(0);
        if (kt + 1 < KT) { R2S(1, 1); __syncthreads(); }
        if (kt + 3 < KT) G2R(1, (kt + 3) * 32);
        if (kt + 1 < KT) {
            COMPUTE(1);
            if (kt + 2 < KT) { R2S(0, 0); __syncthreads(); }
        }
    }
#undef G2R
#undef R2S
#undef COMPUTE

    // epilogue
    const int row0 = bm + m0 + (lane >> 2);
    #pragma unroll
    for (int mt = 0; mt < 2; mt++) {
        int r0 = row0 + mt * 16, r1 = r0 + 8;
        #pragma unroll
        for (int nt = 0; nt < 4; nt++) {
            int col = bn + n0 + nt * 8 + ((lane & 3) << 1);
            float b0 = 0.f, b1 = 0.f;
            if (EPI >= 1) { b0 = __ldg(bias + col); b1 = __ldg(bias + col + 1); }
            float v0 = acc[mt][nt][0] + b0, v1 = acc[mt][nt][1] + b1;
            float v2 = acc[mt][nt][2] + b0, v3 = acc[mt][nt][3] + b1;
            if (EPI == 2) {
                v0 = fmaxf(v0, 0.f); v1 = fmaxf(v1, 0.f);
                v2 = fmaxf(v2, 0.f); v3 = fmaxf(v3, 0.f);
            }
            if (r0 < M) store2(C + (size_t)r0 * N + col, v0, v1);
            if (r1 < M) store2(C + (size_t)r1 * N + col, v2, v3);
        }
    }
}

// ---------------- softmax over groups of 16 (per query, per head) ----------------
__global__ void softmax16_kernel(float* __restrict__ aw) {
    int g = blockIdx.x * blockDim.x + threadIdx.x;
    if (g >= NQ * 8) return;
    float* p = aw + (size_t)g * 16;
    float v[16];
    float mx = -1e30f;
    #pragma unroll
    for (int i = 0; i < 16; i++) { v[i] = p[i]; mx = fmaxf(mx, v[i]); }
    float s = 0.f;
    #pragma unroll
    for (int i = 0; i < 16; i++) { v[i] = expf(v[i] - mx); s += v[i]; }
    float inv = 1.0f / s;
    #pragma unroll
    for (int i = 0; i < 16; i++) p[i] = v[i] * inv;
}

// ---------------- deformable sampling + cross-camera aggregation ----------------
// One block per query. Phase 1: 768 (cam,head,lvl,pt) combos -> corner weights
// + packed clamped coords in smem. Phase 2: thread t = pg*64+g handles channel
// group g (4 channels) and level pg (4 points), loading uint2 (4 bf16) per
// corner. Partial sums reduced across the 4 levels through smem.
__global__ __launch_bounds__(256) void sample_kernel(
    const float* __restrict__ ref)   // (6, 6400, 4, 2)
{
    __shared__ float4 sw[768];
    __shared__ unsigned int sxy[768];
    __shared__ float4 sred[256];
    const int n = blockIdx.x;
    const int tid = threadIdx.x;
    const unsigned int vism = g_vis[n];

    #pragma unroll
    for (int t = 0; t < 3; t++) {
        int cid = tid + t * 256;
        int k = cid >> 7;
        int r = cid & 127;          // h*16 + lvl*4 + p
        int h = r >> 4;
        int lvl = (r >> 2) & 3;
        int p = r & 3;
        float4 wv = make_float4(0.f, 0.f, 0.f, 0.f);
        unsigned int xy = 0;
        if ((vism >> k) & 1) {
            int Wi = c_W[lvl], Hi = c_H[lvl];
            float Wf = (float)Wi, Hf = (float)Hi;
            const float* rp = ref + (((size_t)k * NQ + n) * 4 + lvl) * 2;
            float rx = rp[0], ry = rp[1];
            int oi = ((h * 4 + lvl) * 4 + p) * 2;
            float ox = g_off[n * CH + oi];
            float oy = g_off[n * CH + oi + 1];
            float x = (rx + ox / Wf) * Wf - 0.5f;
            float y = (ry + oy / Hf) * Hf - 0.5f;
            float x0f = floorf(x), y0f = floorf(y);
            float lx = x - x0f, ly = y - y0f;
            int x0 = (int)x0f, y0 = (int)y0f;
            float a = g_aw[n * 128 + r];
            bool vx0 = (x0 >= 0) && (x0 < Wi);
            bool vx1 = (x0 + 1 >= 0) && (x0 + 1 < Wi);
            bool vy0 = (y0 >= 0) && (y0 < Hi);
            bool vy1 = (y0 + 1 >= 0) && (y0 + 1 < Hi);
            float omx = 1.0f - lx, omy = 1.0f - ly;
            wv.x = (vx0 && vy0) ? a * omx * omy : 0.0f;
            wv.y = (vx1 && vy0) ? a * lx * omy : 0.0f;
            wv.z = (vx0 && vy1) ? a * omx * ly : 0.0f;
            wv.w = (vx1 && vy1) ? a * lx * ly : 0.0f;
            int xc0 = min(max(x0, 0), Wi - 1);
            int xc1 = min(max(x0 + 1, 0), Wi - 1);
            int yc0 = min(max(y0, 0), Hi - 1);
            int yc1 = min(max(y0 + 1, 0), Hi - 1);
            xy = (unsigned)xc0 | ((unsigned)xc1 << 8) |
                 ((unsigned)yc0 << 16) | ((unsigned)yc1 << 24);
        }
        sw[cid] = wv;
        sxy[cid] = xy;
    }
    __syncthreads();

    const int pg = tid >> 6;              // level handled by this thread
    const int g = tid & 63;               // channel group (4 channels)
    const int h = g >> 3;                 // head
    const int ch0 = g * 4;
    const int Ws = pg == 0 ? 100 : pg == 1 ? 50 : pg == 2 ? 25 : 13;
    const int Ss = pg == 0 ? 0 : pg == 1 ? 6000 : pg == 2 ? 7500 : 7875;

    float4 acc = make_float4(0.f, 0.f, 0.f, 0.f);
    #pragma unroll 1
    for (int k = 0; k < CAMS; k++) {
        if (!((vism >> k) & 1)) continue;
        const __nv_bfloat16* vb = g_vproj + (size_t)k * (LTOT * CH) + ch0;
        const int base = k * 128 + h * 16 + pg * 4;
        #pragma unroll
        for (int i = 0; i < 4; i++) {
            float4 w = sw[base + i];
            unsigned int xy = sxy[base + i];
            int xc0 = xy & 255, xc1 = (xy >> 8) & 255;
            int yc0 = (xy >> 16) & 255, yc1 = xy >> 24;
            int r0 = Ss + yc0 * Ws, r1 = Ss + yc1 * Ws;
            uint2 q00 = *(const uint2*)(vb + ((size_t)(r0 + xc0) << 8));
            uint2 q01 = *(const uint2*)(vb + ((size_t)(r0 + xc1) << 8));
            uint2 q10 = *(const uint2*)(vb + ((size_t)(r1 + xc0) << 8));
            uint2 q11 = *(const uint2*)(vb + ((size_t)(r1 + xc1) << 8));
            #pragma unroll
            for (int c = 0; c < 1; c++) { }  // (keep compiler from reordering oddly)
            float2 f;
            f = __bfloat1622float2(*(__nv_bfloat162*)&q00.x);
            acc.x = fmaf(w.x, f.x, acc.x); acc.y = fmaf(w.x, f.y, acc.y);
            f = __bfloat1622float2(*(__nv_bfloat162*)&q00.y);
            acc.z = fmaf(w.x, f.x, acc.z); acc.w = fmaf(w.x, f.y, acc.w);
            f = __bfloat1622float2(*(__nv_bfloat162*)&q01.x);
            acc.x = fmaf(w.y, f.x, acc.x); acc.y = fmaf(w.y, f.y, acc.y);
            f = __bfloat1622float2(*(__nv_bfloat162*)&q01.y);
            acc.z = fmaf(w.y, f.x, acc.z); acc.w = fmaf(w.y, f.y, acc.w);
            f = __bfloat1622float2(*(__nv_bfloat162*)&q10.x);
            acc.x = fmaf(w.z, f.x, acc.x); acc.y = fmaf(w.z, f.y, acc.y);
            f = __bfloat1622float2(*(__nv_bfloat162*)&q10.y);
            acc.z = fmaf(w.z, f.x, acc.z); acc.w = fmaf(w.z, f.y, acc.w);
            f = __bfloat1622float2(*(__nv_bfloat162*)&q11.x);
            acc.x = fmaf(w.w, f.x, acc.x); acc.y = fmaf(w.w, f.y, acc.y);
            f = __bfloat1622float2(*(__nv_bfloat162*)&q11.y);
            acc.z = fmaf(w.w, f.x, acc.z); acc.w = fmaf(w.w, f.y, acc.w);
        }
    }
    sred[tid] = acc;
    __syncthreads();
    if (tid < 64) {
        float4 a = sred[tid], b = sred[64 + tid], c = sred[128 + tid], d = sred[192 + tid];
        float4 s;
        s.x = a.x + b.x + c.x + d.x;
        s.y = a.y + b.y + c.y + d.y;
        s.z = a.z + b.z + c.z + d.z;
        s.w = a.w + b.w + c.w + d.w;
        *(float4*)(g_agg + (size_t)n * CH + tid * 4) = s;
    }
}

// ---------------- block reduction helper ----------------
__device__ __forceinline__ float blocksum256(float v, float* sh) {
    #pragma unroll
    for (int o = 16; o > 0; o >>= 1) v += __shfl_xor_sync(0xffffffffu, v, o);
    if ((threadIdx.x & 31) == 0) sh[threadIdx.x >> 5] = v;
    __syncthreads();
    float s = 0.f;
    #pragma unroll
    for (int i = 0; i < 8; i++) s += sh[i];
    __syncthreads();
    return s;
}

// ---------------- slots assembly + residual + LN1 ----------------
__global__ __launch_bounds__(256) void ln1_kernel(
    const float* __restrict__ query, const float* __restrict__ b_out,
    const float* __restrict__ gamma, const float* __restrict__ beta)
{
    __shared__ float sh[8];
    const int n = blockIdx.x, c = threadIdx.x;
    float m = g_cnt[n];
    float q = query[(size_t)n * CH + c];
    float s = m * (q + b_out[c]) + g_proj[(size_t)n * CH + c];
    float t = s / fmaxf(m, 1.0f) + q;
    float mu = blocksum256(t, sh) * (1.0f / CH);
    float d = t - mu;
    float var = blocksum256(d * d, sh) * (1.0f / CH);
    g_x[(size_t)n * CH + c] = d * rsqrtf(var + 1e-5f) * gamma[c] + beta[c];
}

// ---------------- FFN residual + LN2 -> output ----------------
__global__ __launch_bounds__(256) void ln2_kernel(
    const float* __restrict__ gamma, const float* __restrict__ beta,
    float* __restrict__ out)
{
    __shared__ float sh[8];
    const int n = blockIdx.x, c = threadIdx.x;
    float t = g_x[(size_t)n * CH + c] + g_ffn2[(size_t)n * CH + c];
    float mu = blocksum256(t, sh) * (1.0f / CH);
    float d = t - mu;
    float var = blocksum256(d * d, sh) * (1.0f / CH);
    out[(size_t)n * CH + c] = d * rsqrtf(var + 1e-5f) * gamma[c] + beta[c];
}

// ---------------- host launcher ----------------
extern "C" void kernel_launch(void* const* d_in, const int* in_sizes, int n_in,
                              void* d_out, int out_size) {
    const float* query   = (const float*)d_in[0];
    // d_in[1] = key (unused by reference)
    const float* value   = (const float*)d_in[2];
    const float* refpts  = (const float*)d_in[3];
    // d_in[4] spatial_shapes, d_in[5] level_start_index: compile-time constants
    const int*   bev     = (const int*)d_in[6];
    const float* W_value = (const float*)d_in[7];
    const float* b_value = (const float*)d_in[8];
    const float* W_off   = (const float*)d_in[9];
    const float* b_off   = (const float*)d_in[10];
    const float* W_attn  = (const float*)d_in[11];
    const float* b_attn  = (const float*)d_in[12];
    const float* W_out   = (const float*)d_in[13];
    const float* b_out   = (const float*)d_in[14];
    const float* ln1_g   = (const float*)d_in[15];
    const float* ln1_b   = (const float*)d_in[16];
    const float* W1      = (const float*)d_in[17];
    const float* b1      = (const float*)d_in[18];
    const float* W2      = (const float*)d_in[19];
    const float* b2      = (const float*)d_in[20];
    const float* ln2_g   = (const float*)d_in[21];
    const float* ln2_b   = (const float*)d_in[22];
    float* out = (float*)d_out;

    void *p_vproj, *p_off, *p_aw, *p_agg, *p_proj, *p_x, *p_ffn1, *p_ffn2;
    cudaGetSymbolAddress(&p_vproj, g_vproj);
    cudaGetSymbolAddress(&p_off,   g_off);
    cudaGetSymbolAddress(&p_aw,    g_aw);
    cudaGetSymbolAddress(&p_agg,   g_agg);
    cudaGetSymbolAddress(&p_proj,  g_proj);
    cudaGetSymbolAddress(&p_x,     g_x);
    cudaGetSymbolAddress(&p_ffn1,  g_ffn1);
    cudaGetSymbolAddress(&p_ffn2,  g_ffn2);

    // 1. visibility mask + counts
    mask_kernel<<<(NQ + 255) / 256, 256>>>(bev);

    // 2. value projection: (6*7979, 256) @ (256, 256) + b_value -> bf16
    hgemm_kernel<1, __nv_bfloat16><<<dim3((CAMS * LTOT + 127) / 128, CH / 64), 256>>>(
        value, W_value, b_value, (__nv_bfloat16*)p_vproj, CAMS * LTOT, CH, CH);

    // 3. sampling offsets: (6400, 256) @ (256, 256) + b_off
    hgemm_kernel<1, float><<<dim3(NQ / 128, CH / 64), 256>>>(
        query, W_off, b_off, (float*)p_off, NQ, CH, CH);

    // 4. attention logits: (6400, 256) @ (256, 128) + b_attn
    hgemm_kernel<1, float><<<dim3(NQ / 128, 128 / 64), 256>>>(
        query, W_attn, b_attn, (float*)p_aw, NQ, 128, CH);

    // 5. softmax over 16 points per (query, head)
    softmax16_kernel<<<(NQ * 8 + 255) / 256, 256>>>((float*)p_aw);

    // 6. bilinear sampling + cross-camera aggregation
    sample_kernel<<<NQ, 256>>>(refpts);

    // 7. output projection: agg @ W_out (bias folded into ln1)
    hgemm_kernel<0, float><<<dim3(NQ / 128, CH / 64), 256>>>(
        (const float*)p_agg, W_out, nullptr, (float*)p_proj, NQ, CH, CH);

    // 8. slots + residual + LN1
    ln1_kernel<<<NQ, 256>>>(query, b_out, ln1_g, ln1_b);

    // 9. FFN up: relu(x @ W1 + b1)
    hgemm_kernel<2, float><<<dim3(NQ / 128, DFFN / 64), 256>>>(
        (const float*)p_x, W1, b1, (float*)p_ffn1, NQ, DFFN, CH);

    // 10. FFN down: ffn1 @ W2 + b2
    hgemm_kernel<1, float><<<dim3(NQ / 128, CH / 64), 256>>>(
        (const float*)p_ffn1, W2, b2, (float*)p_ffn2, NQ, CH, DFFN);

    // 11. residual + LN2 -> out
    ln2_kernel<<<NQ, 256>>>(ln2_g, ln2_b, out);

    (void)in_sizes; (void)n_in; (void)out_size;
}

// round 4
// speedup vs baseline: 2.3597x; 1.0565x over previous
#include <cuda_runtime.h>
#include <cuda_bf16.h>
#include <stdint.h>

// Problem constants (fixed by setup_inputs)
#define NQ   6400
#define CAMS 6
#define LTOT 7979
#define CH   256
#define DFFN 1024
#define NFUS 384   // fused off(256) + attn-logits(128)

// ---------------- scratch (static device globals; no allocation) ----------------
__device__ __nv_bfloat16 g_vproj[CAMS * LTOT * CH]; // 24.5 MB: value @ W_value + b (bf16)
__device__ float g_Wf[CH * NFUS];             // fused [W_off | W_attn]
__device__ float g_bf[NFUS];                  // fused bias
__device__ float g_fused[NQ * NFUS];          // fused offsets + attn logits
__device__ __nv_bfloat16 g_aggh[NQ * CH];     // aggregated samples (bf16)
__device__ float g_proj[NQ * CH];             // agg @ W_out
__device__ float g_x[NQ * CH];                // after LN1
__device__ __nv_bfloat16 g_ffn1h[NQ * DFFN];  // relu(x@W1+b1) (bf16)
__device__ float g_ffn2[NQ * CH];             // ffn1@W2+b2
__device__ unsigned int g_vis[NQ];            // per-query camera visibility bitmask
__device__ float g_cnt[NQ];                   // number of visible cameras (float)

__constant__ int c_W[4] = {100, 50, 25, 13};
__constant__ int c_H[4] = {60, 30, 15, 8};

// ---------------- visibility mask ----------------
__global__ void mask_kernel(const int* __restrict__ bev) {
    int n = blockIdx.x * blockDim.x + threadIdx.x;
    if (n >= NQ) return;
    unsigned int vm = 0;
    int cnt = 0;
    #pragma unroll
    for (int k = 0; k < CAMS; k++) {
        const int* bp = bev + ((size_t)k * NQ + n) * 4;
        int s = bp[0] + bp[1] + bp[2] + bp[3];
        if (s > 0) { vm |= (1u << k); cnt++; }
    }
    g_vis[n] = vm;
    g_cnt[n] = (float)cnt;
}

// ---------------- fuse W_off|W_attn into one weight matrix ----------------
__global__ void fuse_w_kernel(const float* __restrict__ Woff, const float* __restrict__ Wattn,
                              const float* __restrict__ boff, const float* __restrict__ battn) {
    int i = blockIdx.x * 256 + threadIdx.x;
    if (i < CH * NFUS) {
        int k = i / NFUS, n = i % NFUS;
        g_Wf[i] = (n < 256) ? Woff[k * 256 + n] : Wattn[k * 128 + (n - 256)];
    }
    if (i < NFUS) g_bf[i] = (i < 256) ? boff[i] : battn[i - 256];
}

// ---------------- tensor-core GEMM building blocks ----------------
__device__ __forceinline__ void ldsm4(uint32_t* r, const void* p) {
    uint32_t a = (uint32_t)__cvta_generic_to_shared(p);
    asm volatile("ldmatrix.sync.aligned.m8n8.x4.shared.b16 {%0,%1,%2,%3}, [%4];"
                 : "=r"(r[0]), "=r"(r[1]), "=r"(r[2]), "=r"(r[3]) : "r"(a));
}

__device__ __forceinline__ void mma_bf16(float* d, const uint32_t* a, const uint32_t* b) {
    asm volatile("mma.sync.aligned.m16n8k16.row.col.f32.bf16.bf16.f32 "
                 "{%0,%1,%2,%3}, {%4,%5,%6,%7}, {%8,%9}, {%0,%1,%2,%3};"
                 : "+f"(d[0]), "+f"(d[1]), "+f"(d[2]), "+f"(d[3])
                 : "r"(a[0]), "r"(a[1]), "r"(a[2]), "r"(a[3]), "r"(b[0]), "r"(b[1]));
}

__device__ __forceinline__ void store2(float* C, float x, float y) {
    *(float2*)C = make_float2(x, y);
}
__device__ __forceinline__ void store2(__nv_bfloat16* C, float x, float y) {
    *(__nv_bfloat162*)C = __floats2bfloat162_rn(x, y);
}

// A-tile vector type: fp32 -> float4 (4 cols, convert on store),
// bf16 -> uint2 (4 cols, direct store). Same indexing either way.
template<typename T> struct AVec;
template<> struct AVec<float> { using V = float4; };
template<> struct AVec<__nv_bfloat16> { using V = uint2; };

__device__ __forceinline__ void a2s(__nv_bfloat16* d, float4 v) {
    *(__nv_bfloat162*)d       = __floats2bfloat162_rn(v.x, v.y);
    *(__nv_bfloat162*)(d + 2) = __floats2bfloat162_rn(v.z, v.w);
}
__device__ __forceinline__ void a2s(__nv_bfloat16* d, uint2 v) {
    *(uint32_t*)d       = v.x;
    *(uint32_t*)(d + 2) = v.y;
}

// ---------------- bf16 tensor-core GEMM, pipelined ----------------------------
// C = A(MxK) * B(KxN,f32) (+bias)(+relu). Block tile 128x64, BK=32,
// 256 threads (8 warps x 32x32). Double-buffered smem + 2-deep register
// prefetch. EPI: 0 none, 1 +bias, 2 +bias+relu.
template<int EPI, typename InT, typename OutT>
__global__ __launch_bounds__(256, 2) void hgemm_kernel(
    const InT* __restrict__ A, const float* __restrict__ B,
    const float* __restrict__ bias, OutT* __restrict__ C,
    int M, int N, int K)
{
    using AV = typename AVec<InT>::V;
    __shared__ __align__(16) __nv_bfloat16 As[2][128][40];  // pad 40 -> LDSM conflict-free
    __shared__ __align__(16) __nv_bfloat16 Bs[2][64][40];   // stored [n][k]
    const int tid = threadIdx.x;
    const int bm = blockIdx.x * 128, bn = blockIdx.y * 64;
    const int lane = tid & 31, w = tid >> 5;
    const int m0 = (w >> 1) * 32, n0 = (w & 1) * 32;

    float acc[2][4][4];
    #pragma unroll
    for (int i = 0; i < 2; i++)
        #pragma unroll
        for (int j = 0; j < 4; j++)
            #pragma unroll
            for (int l = 0; l < 4; l++) acc[i][j][l] = 0.0f;

    const int arow = tid >> 3, acol = (tid & 7) * 4;   // A: 4x (32 rows x 32 cols)
    const int bk = tid >> 4, bn4 = (tid & 15) * 4;     // B: 2x (16 k x 64 n)

    const InT* Ap[4];
    #pragma unroll
    for (int p = 0; p < 4; p++) {
        int r = bm + arow + p * 32; r = r < M ? r : M - 1;
        Ap[p] = A + (size_t)r * K + acol;
    }
    const float* Bp0 = B + (size_t)bk * N + bn + bn4;
    const float* Bp1 = Bp0 + (size_t)16 * N;

    AV arg[2][4];
    float4 brg[2][2];

#define G2R(s, k0) do {                                                        \
    _Pragma("unroll")                                                          \
    for (int p = 0; p < 4; p++) arg[s][p] = *(const AV*)(Ap[p] + (k0));        \
    brg[s][0] = *(const float4*)(Bp0 + (size_t)(k0) * N);                      \
    brg[s][1] = *(const float4*)(Bp1 + (size_t)(k0) * N);                      \
} while (0)

#define R2S(s, b) do {                                                         \
    _Pragma("unroll")                                                          \
    for (int p = 0; p < 4; p++)                                                \
        a2s(&As[b][arow + p * 32][acol], arg[s][p]);                           \
    _Pragma("unroll")                                                          \
    for (int p = 0; p < 2; p++) {                                              \
        int kk = bk + p * 16;                                                  \
        Bs[b][bn4 + 0][kk] = __float2bfloat16_rn(brg[s][p].x);                 \
        Bs[b][bn4 + 1][kk] = __float2bfloat16_rn(brg[s][p].y);                 \
        Bs[b][bn4 + 2][kk] = __float2bfloat16_rn(brg[s][p].z);                 \
        Bs[b][bn4 + 3][kk] = __float2bfloat16_rn(brg[s][p].w);                 \
    }                                                                          \
} while (0)

#define COMPUTE(b) do {                                                        \
    _Pragma("unroll")                                                          \
    for (int ks = 0; ks < 2; ks++) {                                           \
        uint32_t af[2][4], bfr[4][2];                                          \
        _Pragma("unroll")                                                      \
        for (int mt = 0; mt < 2; mt++)                                         \
            ldsm4(af[mt], &As[b][m0 + mt * 16 + (lane & 15)]                   \
                             [ks * 16 + ((lane >> 4) << 3)]);                  \
        _Pragma("unroll")                                                      \
        for (int nt2 = 0; nt2 < 2; nt2++) {                                    \
            uint32_t t[4];                                                     \
            ldsm4(t, &Bs[b][n0 + nt2 * 16 + (lane & 15)]                       \
                           [ks * 16 + ((lane >> 4) << 3)]);                    \
            bfr[nt2 * 2][0] = t[0];      bfr[nt2 * 2][1] = t[2];               \
            bfr[nt2 * 2 + 1][0] = t[1];  bfr[nt2 * 2 + 1][1] = t[3];           \
        }                                                                      \
        _Pragma("unroll")                                                      \
        for (int mt = 0; mt < 2; mt++)                                         \
            _Pragma("unroll")                                                  \
            for (int nt = 0; nt < 4; nt++)                                     \
                mma_bf16(acc[mt][nt], af[mt], bfr[nt]);                        \
    }                                                                          \
} while (0)

    const int KT = K >> 5;   // K in {256, 1024} -> KT even
    G2R(0, 0);
    R2S(0, 0);
    G2R(1, 32);
    __syncthreads();

    for (int kt = 0; kt < KT; kt += 2) {
        if (kt + 2 < KT) G2R(0, (kt + 2) * 32);
        COMPUTE(0);
        if (kt + 1 < KT) { R2S(1, 1); __syncthreads(); }
        if (kt + 3 < KT) G2R(1, (kt + 3) * 32);
        if (kt + 1 < KT) {
            COMPUTE(1);
            if (kt + 2 < KT) { R2S(0, 0); __syncthreads(); }
        }
    }
#undef G2R
#undef R2S
#undef COMPUTE

    // epilogue
    const int row0 = bm + m0 + (lane >> 2);
    #pragma unroll
    for (int mt = 0; mt < 2; mt++) {
        int r0 = row0 + mt * 16, r1 = r0 + 8;
        #pragma unroll
        for (int nt = 0; nt < 4; nt++) {
            int col = bn + n0 + nt * 8 + ((lane & 3) << 1);
            float b0 = 0.f, b1 = 0.f;
            if (EPI >= 1) { b0 = __ldg(bias + col); b1 = __ldg(bias + col + 1); }
            float v0 = acc[mt][nt][0] + b0, v1 = acc[mt][nt][1] + b1;
            float v2 = acc[mt][nt][2] + b0, v3 = acc[mt][nt][3] + b1;
            if (EPI == 2) {
                v0 = fmaxf(v0, 0.f); v1 = fmaxf(v1, 0.f);
                v2 = fmaxf(v2, 0.f); v3 = fmaxf(v3, 0.f);
            }
            if (r0 < M) store2(C + (size_t)r0 * N + col, v0, v1);
            if (r1 < M) store2(C + (size_t)r1 * N + col, v2, v3);
        }
    }
}

// ---------------- deformable sampling + cross-camera aggregation ----------------
// One block per query. Phase 0: 16-wide softmax of the attn logits (fused).
// Phase 1: 768 (cam,head,lvl,pt) combos -> corner weights + packed coords.
// Phase 2: thread t = lvl*64+g handles channel group g (4 ch) at level lvl.
__global__ __launch_bounds__(256) void sample_kernel(
    const float* __restrict__ ref)   // (6, 6400, 4, 2)
{
    __shared__ float4 sw[768];
    __shared__ unsigned int sxy[768];
    __shared__ float4 sred[256];
    __shared__ float saw[128];
    const int n = blockIdx.x;
    const int tid = threadIdx.x;
    const unsigned int vism = g_vis[n];

    // Phase 0: softmax over each 16-point group (8 heads)
    if (tid < 128) {
        float lv = g_fused[(size_t)n * NFUS + 256 + tid];
        float mx = lv;
        #pragma unroll
        for (int o = 8; o > 0; o >>= 1)
            mx = fmaxf(mx, __shfl_xor_sync(0xffffffffu, mx, o));
        float e = expf(lv - mx);
        float s = e;
        #pragma unroll
        for (int o = 8; o > 0; o >>= 1)
            s += __shfl_xor_sync(0xffffffffu, s, o);
        saw[tid] = e / s;
    }
    __syncthreads();

    #pragma unroll
    for (int t = 0; t < 3; t++) {
        int cid = tid + t * 256;
        int k = cid >> 7;
        int r = cid & 127;          // h*16 + lvl*4 + p
        int h = r >> 4;
        int lvl = (r >> 2) & 3;
        int p = r & 3;
        float4 wv = make_float4(0.f, 0.f, 0.f, 0.f);
        unsigned int xy = 0;
        if ((vism >> k) & 1) {
            int Wi = c_W[lvl], Hi = c_H[lvl];
            float Wf = (float)Wi, Hf = (float)Hi;
            const float* rp = ref + (((size_t)k * NQ + n) * 4 + lvl) * 2;
            float rx = rp[0], ry = rp[1];
            int oi = ((h * 4 + lvl) * 4 + p) * 2;
            float ox = g_fused[(size_t)n * NFUS + oi];
            float oy = g_fused[(size_t)n * NFUS + oi + 1];
            float x = (rx + ox / Wf) * Wf - 0.5f;
            float y = (ry + oy / Hf) * Hf - 0.5f;
            float x0f = floorf(x), y0f = floorf(y);
            float lx = x - x0f, ly = y - y0f;
            int x0 = (int)x0f, y0 = (int)y0f;
            float a = saw[r];
            bool vx0 = (x0 >= 0) && (x0 < Wi);
            bool vx1 = (x0 + 1 >= 0) && (x0 + 1 < Wi);
            bool vy0 = (y0 >= 0) && (y0 < Hi);
            bool vy1 = (y0 + 1 >= 0) && (y0 + 1 < Hi);
            float omx = 1.0f - lx, omy = 1.0f - ly;
            wv.x = (vx0 && vy0) ? a * omx * omy : 0.0f;
            wv.y = (vx1 && vy0) ? a * lx * omy : 0.0f;
            wv.z = (vx0 && vy1) ? a * omx * ly : 0.0f;
            wv.w = (vx1 && vy1) ? a * lx * ly : 0.0f;
            int xc0 = min(max(x0, 0), Wi - 1);
            int xc1 = min(max(x0 + 1, 0), Wi - 1);
            int yc0 = min(max(y0, 0), Hi - 1);
            int yc1 = min(max(y0 + 1, 0), Hi - 1);
            xy = (unsigned)xc0 | ((unsigned)xc1 << 8) |
                 ((unsigned)yc0 << 16) | ((unsigned)yc1 << 24);
        }
        sw[cid] = wv;
        sxy[cid] = xy;
    }
    __syncthreads();

    const int pg = tid >> 6;              // level handled by this thread
    const int g = tid & 63;               // channel group (4 channels)
    const int h = g >> 3;                 // head
    const int ch0 = g * 4;
    const int Ws = pg == 0 ? 100 : pg == 1 ? 50 : pg == 2 ? 25 : 13;
    const int Ss = pg == 0 ? 0 : pg == 1 ? 6000 : pg == 2 ? 7500 : 7875;

    float4 acc = make_float4(0.f, 0.f, 0.f, 0.f);
    #pragma unroll 1
    for (int k = 0; k < CAMS; k++) {
        if (!((vism >> k) & 1)) continue;
        const __nv_bfloat16* vb = g_vproj + (size_t)k * (LTOT * CH) + ch0;
        const int base = k * 128 + h * 16 + pg * 4;
        #pragma unroll
        for (int i = 0; i < 4; i++) {
            float4 w = sw[base + i];
            unsigned int xy = sxy[base + i];
            int xc0 = xy & 255, xc1 = (xy >> 8) & 255;
            int yc0 = (xy >> 16) & 255, yc1 = xy >> 24;
            int r0 = Ss + yc0 * Ws, r1 = Ss + yc1 * Ws;
            uint2 q00 = *(const uint2*)(vb + ((size_t)(r0 + xc0) << 8));
            uint2 q01 = *(const uint2*)(vb + ((size_t)(r0 + xc1) << 8));
            uint2 q10 = *(const uint2*)(vb + ((size_t)(r1 + xc0) << 8));
            uint2 q11 = *(const uint2*)(vb + ((size_t)(r1 + xc1) << 8));
            float2 f;
            f = __bfloat1622float2(*(__nv_bfloat162*)&q00.x);
            acc.x = fmaf(w.x, f.x, acc.x); acc.y = fmaf(w.x, f.y, acc.y);
            f = __bfloat1622float2(*(__nv_bfloat162*)&q00.y);
            acc.z = fmaf(w.x, f.x, acc.z); acc.w = fmaf(w.x, f.y, acc.w);
            f = __bfloat1622float2(*(__nv_bfloat162*)&q01.x);
            acc.x = fmaf(w.y, f.x, acc.x); acc.y = fmaf(w.y, f.y, acc.y);
            f = __bfloat1622float2(*(__nv_bfloat162*)&q01.y);
            acc.z = fmaf(w.y, f.x, acc.z); acc.w = fmaf(w.y, f.y, acc.w);
            f = __bfloat1622float2(*(__nv_bfloat162*)&q10.x);
            acc.x = fmaf(w.z, f.x, acc.x); acc.y = fmaf(w.z, f.y, acc.y);
            f = __bfloat1622float2(*(__nv_bfloat162*)&q10.y);
            acc.z = fmaf(w.z, f.x, acc.z); acc.w = fmaf(w.z, f.y, acc.w);
            f = __bfloat1622float2(*(__nv_bfloat162*)&q11.x);
            acc.x = fmaf(w.w, f.x, acc.x); acc.y = fmaf(w.w, f.y, acc.y);
            f = __bfloat1622float2(*(__nv_bfloat162*)&q11.y);
            acc.z = fmaf(w.w, f.x, acc.z); acc.w = fmaf(w.w, f.y, acc.w);
        }
    }
    sred[tid] = acc;
    __syncthreads();
    if (tid < 64) {
        float4 a = sred[tid], b = sred[64 + tid], c = sred[128 + tid], d = sred[192 + tid];
        float4 s;
        s.x = a.x + b.x + c.x + d.x;
        s.y = a.y + b.y + c.y + d.y;
        s.z = a.z + b.z + c.z + d.z;
        s.w = a.w + b.w + c.w + d.w;
        __nv_bfloat162 lo = __floats2bfloat162_rn(s.x, s.y);
        __nv_bfloat162 hi = __floats2bfloat162_rn(s.z, s.w);
        uint2 pk;
        pk.x = *(uint32_t*)&lo;
        pk.y = *(uint32_t*)&hi;
        *(uint2*)(g_aggh + (size_t)n * CH + tid * 4) = pk;
    }
}

// ---------------- block reduction helper ----------------
__device__ __forceinline__ float blocksum256(float v, float* sh) {
    #pragma unroll
    for (int o = 16; o > 0; o >>= 1) v += __shfl_xor_sync(0xffffffffu, v, o);
    if ((threadIdx.x & 31) == 0) sh[threadIdx.x >> 5] = v;
    __syncthreads();
    float s = 0.f;
    #pragma unroll
    for (int i = 0; i < 8; i++) s += sh[i];
    __syncthreads();
    return s;
}

// ---------------- slots assembly + residual + LN1 ----------------
__global__ __launch_bounds__(256) void ln1_kernel(
    const float* __restrict__ query, const float* __restrict__ b_out,
    const float* __restrict__ gamma, const float* __restrict__ beta)
{
    __shared__ float sh[8];
    const int n = blockIdx.x, c = threadIdx.x;
    float m = g_cnt[n];
    float q = query[(size_t)n * CH + c];
    float s = m * (q + b_out[c]) + g_proj[(size_t)n * CH + c];
    float t = s / fmaxf(m, 1.0f) + q;
    float mu = blocksum256(t, sh) * (1.0f / CH);
    float d = t - mu;
    float var = blocksum256(d * d, sh) * (1.0f / CH);
    g_x[(size_t)n * CH + c] = d * rsqrtf(var + 1e-5f) * gamma[c] + beta[c];
}

// ---------------- FFN residual + LN2 -> output ----------------
__global__ __launch_bounds__(256) void ln2_kernel(
    const float* __restrict__ gamma, const float* __restrict__ beta,
    float* __restrict__ out)
{
    __shared__ float sh[8];
    const int n = blockIdx.x, c = threadIdx.x;
    float t = g_x[(size_t)n * CH + c] + g_ffn2[(size_t)n * CH + c];
    float mu = blocksum256(t, sh) * (1.0f / CH);
    float d = t - mu;
    float var = blocksum256(d * d, sh) * (1.0f / CH);
    out[(size_t)n * CH + c] = d * rsqrtf(var + 1e-5f) * gamma[c] + beta[c];
}

// ---------------- host launcher ----------------
extern "C" void kernel_launch(void* const* d_in, const int* in_sizes, int n_in,
                              void* d_out, int out_size) {
    const float* query   = (const float*)d_in[0];
    // d_in[1] = key (unused by reference)
    const float* value   = (const float*)d_in[2];
    const float* refpts  = (const float*)d_in[3];
    // d_in[4] spatial_shapes, d_in[5] level_start_index: compile-time constants
    const int*   bev     = (const int*)d_in[6];
    const float* W_value = (const float*)d_in[7];
    const float* b_value = (const float*)d_in[8];
    const float* W_off   = (const float*)d_in[9];
    const float* b_off   = (const float*)d_in[10];
    const float* W_attn  = (const float*)d_in[11];
    const float* b_attn  = (const float*)d_in[12];
    const float* W_out   = (const float*)d_in[13];
    const float* b_out   = (const float*)d_in[14];
    const float* ln1_g   = (const float*)d_in[15];
    const float* ln1_b   = (const float*)d_in[16];
    const float* W1      = (const float*)d_in[17];
    const float* b1      = (const float*)d_in[18];
    const float* W2      = (const float*)d_in[19];
    const float* b2      = (const float*)d_in[20];
    const float* ln2_g   = (const float*)d_in[21];
    const float* ln2_b   = (const float*)d_in[22];
    float* out = (float*)d_out;

    void *p_vproj, *p_Wf, *p_bf, *p_fused, *p_aggh, *p_proj, *p_x, *p_ffn1h, *p_ffn2;
    cudaGetSymbolAddress(&p_vproj,  g_vproj);
    cudaGetSymbolAddress(&p_Wf,     g_Wf);
    cudaGetSymbolAddress(&p_bf,     g_bf);
    cudaGetSymbolAddress(&p_fused,  g_fused);
    cudaGetSymbolAddress(&p_aggh,   g_aggh);
    cudaGetSymbolAddress(&p_proj,   g_proj);
    cudaGetSymbolAddress(&p_x,      g_x);
    cudaGetSymbolAddress(&p_ffn1h,  g_ffn1h);
    cudaGetSymbolAddress(&p_ffn2,   g_ffn2);

    // Side stream + events for the vproj fork (created once, before any capture:
    // the harness's first call is the uncaptured correctness run).
    static cudaStream_t s2 = nullptr;
    static cudaEvent_t ev_fork = nullptr, ev_join = nullptr;
    if (s2 == nullptr) {
        cudaStreamCreateWithFlags(&s2, cudaStreamNonBlocking);
        cudaEventCreateWithFlags(&ev_fork, cudaEventDisableTiming);
        cudaEventCreateWithFlags(&ev_join, cudaEventDisableTiming);
    }

    // ---- fork: vproj GEMM (independent, biggest) on s2 ----
    cudaEventRecord(ev_fork, 0);
    cudaStreamWaitEvent(s2, ev_fork, 0);
    hgemm_kernel<1, float, __nv_bfloat16>
        <<<dim3((CAMS * LTOT + 127) / 128, CH / 64), 256, 0, s2>>>(
        value, W_value, b_value, (__nv_bfloat16*)p_vproj, CAMS * LTOT, CH, CH);
    cudaEventRecord(ev_join, s2);

    // ---- main stream: mask + fused offsets/attn GEMM ----
    mask_kernel<<<(NQ + 255) / 256, 256>>>(bev);
    fuse_w_kernel<<<(CH * NFUS + 255) / 256, 256>>>(W_off, W_attn, b_off, b_attn);
    hgemm_kernel<1, float, float><<<dim3(NQ / 128, NFUS / 64), 256>>>(
        query, (const float*)p_Wf, (const float*)p_bf, (float*)p_fused, NQ, NFUS, CH);

    // ---- join, then sampling (softmax fused inside) ----
    cudaStreamWaitEvent(0, ev_join, 0);
    sample_kernel<<<NQ, 256>>>(refpts);

    // output projection: agg(bf16) @ W_out (bias folded into ln1)
    hgemm_kernel<0, __nv_bfloat16, float><<<dim3(NQ / 128, CH / 64), 256>>>(
        (const __nv_bfloat16*)p_aggh, W_out, nullptr, (float*)p_proj, NQ, CH, CH);

    // slots + residual + LN1
    ln1_kernel<<<NQ, 256>>>(query, b_out, ln1_g, ln1_b);

    // FFN up: relu(x @ W1 + b1) -> bf16
    hgemm_kernel<2, float, __nv_bfloat16><<<dim3(NQ / 128, DFFN / 64), 256>>>(
        (const float*)p_x, W1, b1, (__nv_bfloat16*)p_ffn1h, NQ, DFFN, CH);

    // FFN down: ffn1(bf16) @ W2 + b2
    hgemm_kernel<1, __nv_bfloat16, float><<<dim3(NQ / 128, CH / 64), 256>>>(
        (const __nv_bfloat16*)p_ffn1h, W2, b2, (float*)p_ffn2, NQ, CH, DFFN);

    // residual + LN2 -> out
    ln2_kernel<<<NQ, 256>>>(ln2_g, ln2_b, out);

    (void)in_sizes; (void)n_in; (void)out_size;
}

// round 6
// speedup vs baseline: 2.7112x; 1.1490x over previous
#include <cuda_runtime.h>
#include <cuda_bf16.h>
#include <stdint.h>

// Problem constants (fixed by setup_inputs)
#define NQ   6400
#define CAMS 6
#define LTOT 7979
#define CH   256
#define DFFN 1024
#define NFUS 384   // fused off(256) + attn-logits(128)

// ---------------- scratch (static device globals; no allocation) ----------------
__device__ __nv_bfloat16 g_vproj[CAMS * LTOT * CH]; // 24.5 MB: value @ W_value + b (bf16)
__device__ __nv_bfloat16 g_q_h[NQ * CH];            // query in bf16
__device__ __nv_bfloat16 g_Wf_h[CH * NFUS];         // fused [W_off | W_attn] bf16
__device__ float g_bf[NFUS];                        // fused bias (fp32)
__device__ __nv_bfloat16 g_Wout_h[CH * CH];         // W_out bf16
__device__ __nv_bfloat16 g_W1_h[CH * DFFN];         // W1 bf16
__device__ __nv_bfloat16 g_W2_h[DFFN * CH];         // W2 bf16
__device__ float g_fused[NQ * NFUS];                // fused offsets + attn logits
__device__ __nv_bfloat16 g_aggh[NQ * CH];           // aggregated samples (bf16)
__device__ float g_proj[NQ * CH];                   // agg @ W_out
__device__ float g_x[NQ * CH];                      // after LN1 (fp32, for ln2 residual)
__device__ __nv_bfloat16 g_x_h[NQ * CH];            // after LN1 (bf16, for ffn1 A)
__device__ __nv_bfloat16 g_ffn1h[NQ * DFFN];        // relu(x@W1+b1) (bf16)
__device__ float g_ffn2[NQ * CH];                   // ffn1@W2+b2
__device__ unsigned int g_vis[NQ];                  // per-query camera visibility bitmask
__device__ float g_cnt[NQ];                         // number of visible cameras (float)

__constant__ int c_W[4] = {100, 50, 25, 13};
__constant__ int c_H[4] = {60, 30, 15, 8};

// ---------------- fused prep: mask + all fp32->bf16 conversions ----------------
__global__ __launch_bounds__(256) void prep_kernel(
    const int* __restrict__ bev, const float* __restrict__ query,
    const float* __restrict__ Woff, const float* __restrict__ Wattn,
    const float* __restrict__ boff, const float* __restrict__ battn,
    const float* __restrict__ Wout, const float* __restrict__ W1,
    const float* __restrict__ W2)
{
    const int b = blockIdx.x, tid = threadIdx.x;
    if (b < 25) {
        int n = b * 256 + tid;
        unsigned int vm = 0; int cnt = 0;
        #pragma unroll
        for (int k = 0; k < CAMS; k++) {
            const int* bp = bev + ((size_t)k * NQ + n) * 4;
            if (bp[0] + bp[1] + bp[2] + bp[3] > 0) { vm |= (1u << k); cnt++; }
        }
        g_vis[n] = vm;
        g_cnt[n] = (float)cnt;
    } else if (b < 1625) {
        int i = (b - 25) * 256 + tid;           // float4 index, < 409600
        float4 v = ((const float4*)query)[i];
        ((__nv_bfloat162*)g_q_h)[i * 2]     = __floats2bfloat162_rn(v.x, v.y);
        ((__nv_bfloat162*)g_q_h)[i * 2 + 1] = __floats2bfloat162_rn(v.z, v.w);
    } else if (b < 2009) {
        int i = (b - 1625) * 256 + tid;         // < 98304
        int k = i / NFUS, n = i % NFUS;
        float v = (n < 256) ? Woff[k * 256 + n] : Wattn[k * 128 + (n - 256)];
        g_Wf_h[i] = __float2bfloat16_rn(v);
        if (i < NFUS) g_bf[i] = (i < 256) ? boff[i] : battn[i - 256];
    } else if (b < 2073) {
        int i = (b - 2009) * 256 + tid;         // < 16384
        float4 v = ((const float4*)Wout)[i];
        ((__nv_bfloat162*)g_Wout_h)[i * 2]     = __floats2bfloat162_rn(v.x, v.y);
        ((__nv_bfloat162*)g_Wout_h)[i * 2 + 1] = __floats2bfloat162_rn(v.z, v.w);
    } else if (b < 2329) {
        int i = (b - 2073) * 256 + tid;         // < 65536
        float4 v = ((const float4*)W1)[i];
        ((__nv_bfloat162*)g_W1_h)[i * 2]     = __floats2bfloat162_rn(v.x, v.y);
        ((__nv_bfloat162*)g_W1_h)[i * 2 + 1] = __floats2bfloat162_rn(v.z, v.w);
    } else {
        int i = (b - 2329) * 256 + tid;         // < 65536
        float4 v = ((const float4*)W2)[i];
        ((__nv_bfloat162*)g_W2_h)[i * 2]     = __floats2bfloat162_rn(v.x, v.y);
        ((__nv_bfloat162*)g_W2_h)[i * 2 + 1] = __floats2bfloat162_rn(v.z, v.w);
    }
}

// ---------------- tensor-core GEMM building blocks ----------------
__device__ __forceinline__ void ldsm4(uint32_t* r, const void* p) {
    uint32_t a = (uint32_t)__cvta_generic_to_shared(p);
    asm volatile("ldmatrix.sync.aligned.m8n8.x4.shared.b16 {%0,%1,%2,%3}, [%4];"
                 : "=r"(r[0]), "=r"(r[1]), "=r"(r[2]), "=r"(r[3]) : "r"(a));
}
__device__ __forceinline__ void ldsm4t(uint32_t* r, const void* p) {
    uint32_t a = (uint32_t)__cvta_generic_to_shared(p);
    asm volatile("ldmatrix.sync.aligned.m8n8.x4.trans.shared.b16 {%0,%1,%2,%3}, [%4];"
                 : "=r"(r[0]), "=r"(r[1]), "=r"(r[2]), "=r"(r[3]) : "r"(a));
}
__device__ __forceinline__ void mma_bf16(float* d, const uint32_t* a, const uint32_t* b) {
    asm volatile("mma.sync.aligned.m16n8k16.row.col.f32.bf16.bf16.f32 "
                 "{%0,%1,%2,%3}, {%4,%5,%6,%7}, {%8,%9}, {%0,%1,%2,%3};"
                 : "+f"(d[0]), "+f"(d[1]), "+f"(d[2]), "+f"(d[3])
                 : "r"(a[0]), "r"(a[1]), "r"(a[2]), "r"(a[3]), "r"(b[0]), "r"(b[1]));
}
__device__ __forceinline__ void cpa16(void* dst, const void* src) {
    uint32_t d = (uint32_t)__cvta_generic_to_shared(dst);
    asm volatile("cp.async.cg.shared.global [%0], [%1], 16;" :: "r"(d), "l"(src));
}
__device__ __forceinline__ void store2(float* C, float x, float y) {
    *(float2*)C = make_float2(x, y);
}
__device__ __forceinline__ void store2(__nv_bfloat16* C, float x, float y) {
    *(__nv_bfloat162*)C = __floats2bfloat162_rn(x, y);
}

// ================== bf16 cp.async GEMM ==================
// C(MxN) = A(MxK,bf16 row-major) * B(KxN,bf16 row-major) (+bias)(+relu)
// Block tile 128x64, BK=32, 4-stage cp.async pipeline, 256 threads
// (8 warps x 32x32). Requires M%128==0, N%64==0, K%32==0.
// EPI: 0 none, 1 +bias, 2 +bias+relu.
#define STAGES 4
template<int EPI, typename OutT>
__global__ __launch_bounds__(256, 2) void hgemm_bf16(
    const __nv_bfloat16* __restrict__ A, const __nv_bfloat16* __restrict__ B,
    const float* __restrict__ bias, OutT* __restrict__ C,
    int M, int N, int K)
{
    __shared__ __align__(16) __nv_bfloat16 As[STAGES][128][40];  // 80B rows (16B mult)
    __shared__ __align__(16) __nv_bfloat16 Bs[STAGES][32][72];   // [k][n], 144B rows
    const int tid = threadIdx.x;
    const int bm = blockIdx.x * 128, bn = blockIdx.y * 64;
    const int lane = tid & 31, w = tid >> 5;
    const int m0 = (w >> 1) * 32, n0 = (w & 1) * 32;

    float acc[2][4][4];
    #pragma unroll
    for (int i = 0; i < 2; i++)
        #pragma unroll
        for (int j = 0; j < 4; j++)
            #pragma unroll
            for (int l = 0; l < 4; l++) acc[i][j][l] = 0.0f;

    // A copy mapping: 128 rows x 32 cols = 512 x 16B chunks, 2 per thread
    const int arow = tid >> 1, acol = (tid & 1) * 16;
    // B copy mapping: 32 rows x 64 cols = 256 x 16B chunks, 1 per thread
    const int brow = tid >> 3, bcol = (tid & 7) * 8;

    const __nv_bfloat16* Asrc = A + (size_t)(bm + arow) * K + acol;
    const __nv_bfloat16* Bsrc = B + bn + bcol;

    const int KT = K >> 5;

#define ISSUE(s, kt) do {                                                      \
    cpa16(&As[s][arow][acol],     Asrc + (kt) * 32);                           \
    cpa16(&As[s][arow][acol + 8], Asrc + (kt) * 32 + 8);                       \
    cpa16(&Bs[s][brow][bcol],     Bsrc + (size_t)((kt) * 32 + brow) * N);      \
} while (0)

#define COMPUTE_T(b) do {                                                      \
    _Pragma("unroll")                                                          \
    for (int ks = 0; ks < 2; ks++) {                                           \
        uint32_t af[2][4], bfr[4][2];                                          \
        _Pragma("unroll")                                                      \
        for (int mt = 0; mt < 2; mt++)                                         \
            ldsm4(af[mt], &As[b][m0 + mt * 16 + (lane & 15)]                   \
                             [ks * 16 + ((lane >> 4) << 3)]);                  \
        _Pragma("unroll")                                                      \
        for (int nt2 = 0; nt2 < 2; nt2++) {                                    \
            uint32_t t[4];                                                     \
            ldsm4t(t, &Bs[b][ks * 16 + (lane & 7) + 8 * ((lane >> 3) & 1)]     \
                            [n0 + nt2 * 16 + 8 * (lane >> 4)]);                \
            bfr[nt2 * 2][0] = t[0];      bfr[nt2 * 2][1] = t[1];               \
            bfr[nt2 * 2 + 1][0] = t[2];  bfr[nt2 * 2 + 1][1] = t[3];           \
        }                                                                      \
        _Pragma("unroll")                                                      \
        for (int mt = 0; mt < 2; mt++)                                         \
            _Pragma("unroll")                                                  \
            for (int nt = 0; nt < 4; nt++)                                     \
                mma_bf16(acc[mt][nt], af[mt], bfr[nt]);                        \
    }                                                                          \
} while (0)

    // prologue: fill STAGES-1 stages
    #pragma unroll
    for (int s = 0; s < STAGES - 1; s++) {
        if (s < KT) ISSUE(s, s);
        asm volatile("cp.async.commit_group;");
    }

    for (int kt = 0; kt < KT; kt++) {
        asm volatile("cp.async.wait_group %0;" :: "n"(STAGES - 2));
        __syncthreads();
        int kn = kt + STAGES - 1;
        if (kn < KT) ISSUE(kn & (STAGES - 1), kn);
        asm volatile("cp.async.commit_group;");
        COMPUTE_T(kt & (STAGES - 1));
    }
#undef ISSUE
#undef COMPUTE_T

    // epilogue
    const int row0 = bm + m0 + (lane >> 2);
    #pragma unroll
    for (int mt = 0; mt < 2; mt++) {
        int r0 = row0 + mt * 16, r1 = r0 + 8;
        #pragma unroll
        for (int nt = 0; nt < 4; nt++) {
            int col = bn + n0 + nt * 8 + ((lane & 3) << 1);
            float b0 = 0.f, b1 = 0.f;
            if (EPI >= 1) { b0 = __ldg(bias + col); b1 = __ldg(bias + col + 1); }
            float v0 = acc[mt][nt][0] + b0, v1 = acc[mt][nt][1] + b1;
            float v2 = acc[mt][nt][2] + b0, v3 = acc[mt][nt][3] + b1;
            if (EPI == 2) {
                v0 = fmaxf(v0, 0.f); v1 = fmaxf(v1, 0.f);
                v2 = fmaxf(v2, 0.f); v3 = fmaxf(v3, 0.f);
            }
            store2(C + (size_t)r0 * N + col, v0, v1);
            store2(C + (size_t)r1 * N + col, v2, v3);
        }
    }
}

// ================== fp32-input GEMM (vproj only) ==================
__global__ __launch_bounds__(256, 2) void hgemm_f32(
    const float* __restrict__ A, const float* __restrict__ B,
    const float* __restrict__ bias, __nv_bfloat16* __restrict__ C,
    int M, int N, int K)
{
    __shared__ __align__(16) __nv_bfloat16 As[2][128][40];
    __shared__ __align__(16) __nv_bfloat16 Bs[2][64][40];   // [n][k]
    const int tid = threadIdx.x;
    const int bm = blockIdx.x * 128, bn = blockIdx.y * 64;
    const int lane = tid & 31, w = tid >> 5;
    const int m0 = (w >> 1) * 32, n0 = (w & 1) * 32;

    float acc[2][4][4];
    #pragma unroll
    for (int i = 0; i < 2; i++)
        #pragma unroll
        for (int j = 0; j < 4; j++)
            #pragma unroll
            for (int l = 0; l < 4; l++) acc[i][j][l] = 0.0f;

    const int arow = tid >> 3, acol = (tid & 7) * 4;
    const int bk = tid >> 4, bn4 = (tid & 15) * 4;

    const float* Ap[4];
    #pragma unroll
    for (int p = 0; p < 4; p++) {
        int r = bm + arow + p * 32; r = r < M ? r : M - 1;
        Ap[p] = A + (size_t)r * K + acol;
    }
    const float* Bp0 = B + (size_t)bk * N + bn + bn4;
    const float* Bp1 = Bp0 + (size_t)16 * N;

    float4 arg[2][4];
    float4 brg[2][2];

#define G2R(s, k0) do {                                                        \
    _Pragma("unroll")                                                          \
    for (int p = 0; p < 4; p++) arg[s][p] = *(const float4*)(Ap[p] + (k0));    \
    brg[s][0] = *(const float4*)(Bp0 + (size_t)(k0) * N);                      \
    brg[s][1] = *(const float4*)(Bp1 + (size_t)(k0) * N);                      \
} while (0)

#define R2S(s, b) do {                                                         \
    _Pragma("unroll")                                                          \
    for (int p = 0; p < 4; p++) {                                              \
        int row = arow + p * 32;                                               \
        *(__nv_bfloat162*)&As[b][row][acol] =                                  \
            __floats2bfloat162_rn(arg[s][p].x, arg[s][p].y);                   \
        *(__nv_bfloat162*)&As[b][row][acol + 2] =                              \
            __floats2bfloat162_rn(arg[s][p].z, arg[s][p].w);                   \
    }                                                                          \
    _Pragma("unroll")                                                          \
    for (int p = 0; p < 2; p++) {                                              \
        int kk = bk + p * 16;                                                  \
        Bs[b][bn4 + 0][kk] = __float2bfloat16_rn(brg[s][p].x);                 \
        Bs[b][bn4 + 1][kk] = __float2bfloat16_rn(brg[s][p].y);                 \
        Bs[b][bn4 + 2][kk] = __float2bfloat16_rn(brg[s][p].z);                 \
        Bs[b][bn4 + 3][kk] = __float2bfloat16_rn(brg[s][p].w);                 \
    }                                                                          \
} while (0)

#define COMPUTE(b) do {                                                        \
    _Pragma("unroll")                                                          \
    for (int ks = 0; ks < 2; ks++) {                                           \
        uint32_t af[2][4], bfr[4][2];                                          \
        _Pragma("unroll")                                                      \
        for (int mt = 0; mt < 2; mt++)                                         \
            ldsm4(af[mt], &As[b][m0 + mt * 16 + (lane & 15)]                   \
                             [ks * 16 + ((lane >> 4) << 3)]);                  \
        _Pragma("unroll")                                                      \
        for (int nt2 = 0; nt2 < 2; nt2++) {                                    \
            uint32_t t[4];                                                     \
            ldsm4(t, &Bs[b][n0 + nt2 * 16 + (lane & 15)]                       \
                           [ks * 16 + ((lane >> 4) << 3)]);                    \
            bfr[nt2 * 2][0] = t[0];      bfr[nt2 * 2][1] = t[2];               \
            bfr[nt2 * 2 + 1][0] = t[1];  bfr[nt2 * 2 + 1][1] = t[3];           \
        }                                                                      \
        _Pragma("unroll")                                                      \
        for (int mt = 0; mt < 2; mt++)                                         \
            _Pragma("unroll")                                                  \
            for (int nt = 0; nt < 4; nt++)                                     \
                mma_bf16(acc[mt][nt], af[mt], bfr[nt]);                        \
    }                                                                          \
} while (0)

    const int KT = K >> 5;
    G2R(0, 0);
    R2S(0, 0);
    G2R(1, 32);
    __syncthreads();

    for (int kt = 0; kt < KT; kt += 2) {
        if (kt + 2 < KT) G2R(0, (kt + 2) * 32);
        COMPUTE(0);
        if (kt + 1 < KT) { R2S(1, 1); __syncthreads(); }
        if (kt + 3 < KT) G2R(1, (kt + 3) * 32);
        if (kt + 1 < KT) {
            COMPUTE(1);
            if (kt + 2 < KT) { R2S(0, 0); __syncthreads(); }
        }
    }
#undef G2R
#undef R2S
#undef COMPUTE

    const int row0 = bm + m0 + (lane >> 2);
    #pragma unroll
    for (int mt = 0; mt < 2; mt++) {
        int r0 = row0 + mt * 16, r1 = r0 + 8;
        #pragma unroll
        for (int nt = 0; nt < 4; nt++) {
            int col = bn + n0 + nt * 8 + ((lane & 3) << 1);
            float b0 = __ldg(bias + col), b1 = __ldg(bias + col + 1);
            float v0 = acc[mt][nt][0] + b0, v1 = acc[mt][nt][1] + b1;
            float v2 = acc[mt][nt][2] + b0, v3 = acc[mt][nt][3] + b1;
            if (r0 < M) store2(C + (size_t)r0 * N + col, v0, v1);
            if (r1 < M) store2(C + (size_t)r1 * N + col, v2, v3);
        }
    }
}

// ---------------- deformable sampling + cross-camera aggregation ----------------
__global__ __launch_bounds__(256) void sample_kernel(
    const float* __restrict__ ref)   // (6, 6400, 4, 2)
{
    __shared__ float4 sw[768];
    __shared__ unsigned int sxy[768];
    __shared__ float4 sred[256];
    __shared__ float saw[128];
    const int n = blockIdx.x;
    const int tid = threadIdx.x;
    const unsigned int vism = g_vis[n];

    // Phase 0: softmax over each 16-point group (8 heads)
    if (tid < 128) {
        float lv = g_fused[(size_t)n * NFUS + 256 + tid];
        float mx = lv;
        #pragma unroll
        for (int o = 8; o > 0; o >>= 1)
            mx = fmaxf(mx, __shfl_xor_sync(0xffffffffu, mx, o));
        float e = expf(lv - mx);
        float s = e;
        #pragma unroll
        for (int o = 8; o > 0; o >>= 1)
            s += __shfl_xor_sync(0xffffffffu, s, o);
        saw[tid] = e / s;
    }
    __syncthreads();

    #pragma unroll
    for (int t = 0; t < 3; t++) {
        int cid = tid + t * 256;
        int k = cid >> 7;
        int r = cid & 127;          // h*16 + lvl*4 + p
        int h = r >> 4;
        int lvl = (r >> 2) & 3;
        int p = r & 3;
        float4 wv = make_float4(0.f, 0.f, 0.f, 0.f);
        unsigned int xy = 0;
        if ((vism >> k) & 1) {
            int Wi = c_W[lvl], Hi = c_H[lvl];
            float Wf = (float)Wi, Hf = (float)Hi;
            const float* rp = ref + (((size_t)k * NQ + n) * 4 + lvl) * 2;
            float rx = rp[0], ry = rp[1];
            int oi = ((h * 4 + lvl) * 4 + p) * 2;
            float ox = g_fused[(size_t)n * NFUS + oi];
            float oy = g_fused[(size_t)n * NFUS + oi + 1];
            float x = (rx + ox / Wf) * Wf - 0.5f;
            float y = (ry + oy / Hf) * Hf - 0.5f;
            float x0f = floorf(x), y0f = floorf(y);
            float lx = x - x0f, ly = y - y0f;
            int x0 = (int)x0f, y0 = (int)y0f;
            float a = saw[r];
            bool vx0 = (x0 >= 0) && (x0 < Wi);
            bool vx1 = (x0 + 1 >= 0) && (x0 + 1 < Wi);
            bool vy0 = (y0 >= 0) && (y0 < Hi);
            bool vy1 = (y0 + 1 >= 0) && (y0 + 1 < Hi);
            float omx = 1.0f - lx, omy = 1.0f - ly;
            wv.x = (vx0 && vy0) ? a * omx * omy : 0.0f;
            wv.y = (vx1 && vy0) ? a * lx * omy : 0.0f;
            wv.z = (vx0 && vy1) ? a * omx * ly : 0.0f;
            wv.w = (vx1 && vy1) ? a * lx * ly : 0.0f;
            int xc0 = min(max(x0, 0), Wi - 1);
            int xc1 = min(max(x0 + 1, 0), Wi - 1);
            int yc0 = min(max(y0, 0), Hi - 1);
            int yc1 = min(max(y0 + 1, 0), Hi - 1);
            xy = (unsigned)xc0 | ((unsigned)xc1 << 8) |
                 ((unsigned)yc0 << 16) | ((unsigned)yc1 << 24);
        }
        sw[cid] = wv;
        sxy[cid] = xy;
    }
    __syncthreads();

    const int pg = tid >> 6;              // level handled by this thread
    const int g = tid & 63;               // channel group (4 channels)
    const int h = g >> 3;                 // head
    const int ch0 = g * 4;
    const int Ws = pg == 0 ? 100 : pg == 1 ? 50 : pg == 2 ? 25 : 13;
    const int Ss = pg == 0 ? 0 : pg == 1 ? 6000 : pg == 2 ? 7500 : 7875;

    float4 acc = make_float4(0.f, 0.f, 0.f, 0.f);
    #pragma unroll 1
    for (int k = 0; k < CAMS; k++) {
        if (!((vism >> k) & 1)) continue;
        const __nv_bfloat16* vb = g_vproj + (size_t)k * (LTOT * CH) + ch0;
        const int base = k * 128 + h * 16 + pg * 4;
        #pragma unroll
        for (int i = 0; i < 4; i++) {
            float4 w = sw[base + i];
            unsigned int xy = sxy[base + i];
            int xc0 = xy & 255, xc1 = (xy >> 8) & 255;
            int yc0 = (xy >> 16) & 255, yc1 = xy >> 24;
            int r0 = Ss + yc0 * Ws, r1 = Ss + yc1 * Ws;
            uint2 q00 = *(const uint2*)(vb + ((size_t)(r0 + xc0) << 8));
            uint2 q01 = *(const uint2*)(vb + ((size_t)(r0 + xc1) << 8));
            uint2 q10 = *(const uint2*)(vb + ((size_t)(r1 + xc0) << 8));
            uint2 q11 = *(const uint2*)(vb + ((size_t)(r1 + xc1) << 8));
            float2 f;
            f = __bfloat1622float2(*(__nv_bfloat162*)&q00.x);
            acc.x = fmaf(w.x, f.x, acc.x); acc.y = fmaf(w.x, f.y, acc.y);
            f = __bfloat1622float2(*(__nv_bfloat162*)&q00.y);
            acc.z = fmaf(w.x, f.x, acc.z); acc.w = fmaf(w.x, f.y, acc.w);
            f = __bfloat1622float2(*(__nv_bfloat162*)&q01.x);
            acc.x = fmaf(w.y, f.x, acc.x); acc.y = fmaf(w.y, f.y, acc.y);
            f = __bfloat1622float2(*(__nv_bfloat162*)&q01.y);
            acc.z = fmaf(w.y, f.x, acc.z); acc.w = fmaf(w.y, f.y, acc.w);
            f = __bfloat1622float2(*(__nv_bfloat162*)&q10.x);
            acc.x = fmaf(w.z, f.x, acc.x); acc.y = fmaf(w.z, f.y, acc.y);
            f = __bfloat1622float2(*(__nv_bfloat162*)&q10.y);
            acc.z = fmaf(w.z, f.x, acc.z); acc.w = fmaf(w.z, f.y, acc.w);
            f = __bfloat1622float2(*(__nv_bfloat162*)&q11.x);
            acc.x = fmaf(w.w, f.x, acc.x); acc.y = fmaf(w.w, f.y, acc.y);
            f = __bfloat1622float2(*(__nv_bfloat162*)&q11.y);
            acc.z = fmaf(w.w, f.x, acc.z); acc.w = fmaf(w.w, f.y, acc.w);
        }
    }
    sred[tid] = acc;
    __syncthreads();
    if (tid < 64) {
        float4 a = sred[tid], b = sred[64 + tid], c = sred[128 + tid], d = sred[192 + tid];
        float4 s;
        s.x = a.x + b.x + c.x + d.x;
        s.y = a.y + b.y + c.y + d.y;
        s.z = a.z + b.z + c.z + d.z;
        s.w = a.w + b.w + c.w + d.w;
        __nv_bfloat162 lo = __floats2bfloat162_rn(s.x, s.y);
        __nv_bfloat162 hi = __floats2bfloat162_rn(s.z, s.w);
        uint2 pk;
        pk.x = *(uint32_t*)&lo;
        pk.y = *(uint32_t*)&hi;
        *(uint2*)(g_aggh + (size_t)n * CH + tid * 4) = pk;
    }
}

// ---------------- block reduction helper ----------------
__device__ __forceinline__ float blocksum256(float v, float* sh) {
    #pragma unroll
    for (int o = 16; o > 0; o >>= 1) v += __shfl_xor_sync(0xffffffffu, v, o);
    if ((threadIdx.x & 31) == 0) sh[threadIdx.x >> 5] = v;
    __syncthreads();
    float s = 0.f;
    #pragma unroll
    for (int i = 0; i < 8; i++) s += sh[i];
    __syncthreads();
    return s;
}

// ---------------- slots assembly + residual + LN1 ----------------
__global__ __launch_bounds__(256) void ln1_kernel(
    const float* __restrict__ query, const float* __restrict__ b_out,
    const float* __restrict__ gamma, const float* __restrict__ beta)
{
    __shared__ float sh[8];
    const int n = blockIdx.x, c = threadIdx.x;
    float m = g_cnt[n];
    float q = query[(size_t)n * CH + c];
    float s = m * (q + b_out[c]) + g_proj[(size_t)n * CH + c];
    float t = s / fmaxf(m, 1.0f) + q;
    float mu = blocksum256(t, sh) * (1.0f / CH);
    float d = t - mu;
    float var = blocksum256(d * d, sh) * (1.0f / CH);
    float xv = d * rsqrtf(var + 1e-5f) * gamma[c] + beta[c];
    g_x[(size_t)n * CH + c] = xv;
    g_x_h[(size_t)n * CH + c] = __float2bfloat16_rn(xv);
}

// ---------------- FFN residual + LN2 -> output ----------------
__global__ __launch_bounds__(256) void ln2_kernel(
    const float* __restrict__ gamma, const float* __restrict__ beta,
    float* __restrict__ out)
{
    __shared__ float sh[8];
    const int n = blockIdx.x, c = threadIdx.x;
    float t = g_x[(size_t)n * CH + c] + g_ffn2[(size_t)n * CH + c];
    float mu = blocksum256(t, sh) * (1.0f / CH);
    float d = t - mu;
    float var = blocksum256(d * d, sh) * (1.0f / CH);
    out[(size_t)n * CH + c] = d * rsqrtf(var + 1e-5f) * gamma[c] + beta[c];
}

// ---------------- host launcher ----------------
extern "C" void kernel_launch(void* const* d_in, const int* in_sizes, int n_in,
                              void* d_out, int out_size) {
    const float* query   = (const float*)d_in[0];
    // d_in[1] = key (unused by reference)
    const float* value   = (const float*)d_in[2];
    const float* refpts  = (const float*)d_in[3];
    // d_in[4] spatial_shapes, d_in[5] level_start_index: compile-time constants
    const int*   bev     = (const int*)d_in[6];
    const float* W_value = (const float*)d_in[7];
    const float* b_value = (const float*)d_in[8];
    const float* W_off   = (const float*)d_in[9];
    const float* b_off   = (const float*)d_in[10];
    const float* W_attn  = (const float*)d_in[11];
    const float* b_attn  = (const float*)d_in[12];
    const float* W_out   = (const float*)d_in[13];
    const float* b_out   = (const float*)d_in[14];
    const float* ln1_g   = (const float*)d_in[15];
    const float* ln1_b   = (const float*)d_in[16];
    const float* W1      = (const float*)d_in[17];
    const float* b1      = (const float*)d_in[18];
    const float* W2      = (const float*)d_in[19];
    const float* b2      = (const float*)d_in[20];
    const float* ln2_g   = (const float*)d_in[21];
    const float* ln2_b   = (const float*)d_in[22];
    float* out = (float*)d_out;

    void *p_vproj, *p_qh, *p_Wfh, *p_bf, *p_Wouth, *p_W1h, *p_W2h;
    void *p_fused, *p_aggh, *p_proj, *p_xh, *p_ffn1h, *p_ffn2;
    cudaGetSymbolAddress(&p_vproj,  g_vproj);
    cudaGetSymbolAddress(&p_qh,     g_q_h);
    cudaGetSymbolAddress(&p_Wfh,    g_Wf_h);
    cudaGetSymbolAddress(&p_bf,     g_bf);
    cudaGetSymbolAddress(&p_Wouth,  g_Wout_h);
    cudaGetSymbolAddress(&p_W1h,    g_W1_h);
    cudaGetSymbolAddress(&p_W2h,    g_W2_h);
    cudaGetSymbolAddress(&p_fused,  g_fused);
    cudaGetSymbolAddress(&p_aggh,   g_aggh);
    cudaGetSymbolAddress(&p_proj,   g_proj);
    cudaGetSymbolAddress(&p_xh,     g_x_h);
    cudaGetSymbolAddress(&p_ffn1h,  g_ffn1h);
    cudaGetSymbolAddress(&p_ffn2,   g_ffn2);   // FIX: was passed as host-side &g_ffn2

    static cudaStream_t s2 = nullptr;
    static cudaEvent_t ev_fork = nullptr, ev_join = nullptr;
    if (s2 == nullptr) {
        cudaStreamCreateWithFlags(&s2, cudaStreamNonBlocking);
        cudaEventCreateWithFlags(&ev_fork, cudaEventDisableTiming);
        cudaEventCreateWithFlags(&ev_join, cudaEventDisableTiming);
    }

    // ---- fork: vproj GEMM (independent, biggest) on s2 ----
    cudaEventRecord(ev_fork, 0);
    cudaStreamWaitEvent(s2, ev_fork, 0);
    hgemm_f32<<<dim3((CAMS * LTOT + 127) / 128, CH / 64), 256, 0, s2>>>(
        value, W_value, b_value, (__nv_bfloat16*)p_vproj, CAMS * LTOT, CH, CH);
    cudaEventRecord(ev_join, s2);

    // ---- main stream: prep (mask + all conversions) + fused off/attn GEMM ----
    prep_kernel<<<2585, 256>>>(bev, query, W_off, W_attn, b_off, b_attn,
                               W_out, W1, W2);
    hgemm_bf16<1, float><<<dim3(NQ / 128, NFUS / 64), 256>>>(
        (const __nv_bfloat16*)p_qh, (const __nv_bfloat16*)p_Wfh,
        (const float*)p_bf, (float*)p_fused, NQ, NFUS, CH);

    // ---- join, then sampling (softmax fused inside) ----
    cudaStreamWaitEvent(0, ev_join, 0);
    sample_kernel<<<NQ, 256>>>(refpts);

    // output projection: agg(bf16) @ W_out (bias folded into ln1)
    hgemm_bf16<0, float><<<dim3(NQ / 128, CH / 64), 256>>>(
        (const __nv_bfloat16*)p_aggh, (const __nv_bfloat16*)p_Wouth,
        nullptr, (float*)p_proj, NQ, CH, CH);

    // slots + residual + LN1
    ln1_kernel<<<NQ, 256>>>(query, b_out, ln1_g, ln1_b);

    // FFN up: relu(x @ W1 + b1) -> bf16
    hgemm_bf16<2, __nv_bfloat16><<<dim3(NQ / 128, DFFN / 64), 256>>>(
        (const __nv_bfloat16*)p_xh, (const __nv_bfloat16*)p_W1h,
        b1, (__nv_bfloat16*)p_ffn1h, NQ, DFFN, CH);

    // FFN down: ffn1(bf16) @ W2 + b2
    hgemm_bf16<1, float><<<dim3(NQ / 128, CH / 64), 256>>>(
        (const __nv_bfloat16*)p_ffn1h, (const __nv_bfloat16*)p_W2h,
        b2, (float*)p_ffn2, NQ, CH, DFFN);

    // residual + LN2 -> out
    ln2_kernel<<<NQ, 256>>>(ln2_g, ln2_b, out);

    (void)in_sizes; (void)n_in; (void)out_size;
}

// round 7
// speedup vs baseline: 3.0547x; 1.1267x over previous
#include <cuda_runtime.h>
#include <cuda_bf16.h>
#include <stdint.h>

// Problem constants (fixed by setup_inputs)
#define NQ   6400
#define CAMS 6
#define LTOT 7979
#define CH   256
#define DFFN 1024
#define NFUS 384   // fused off(256) + attn-logits(128)
#define MVAL (CAMS * LTOT)   // 47874
#define MPAD 48000           // 375 * 128

typedef unsigned long long u64;

// ---------------- scratch (static device globals; no allocation) ----------------
__device__ __nv_bfloat16 g_val_h[MPAD * CH];        // value in bf16 (padded rows stay 0)
__device__ __nv_bfloat16 g_Wval_h[CH * CH];         // W_value bf16
__device__ __nv_bfloat16 g_vproj[MPAD * CH];        // value @ W_value + b (bf16)
__device__ __nv_bfloat16 g_q_h[NQ * CH];            // query in bf16
__device__ __nv_bfloat16 g_Wf_h[CH * NFUS];         // fused [W_off | W_attn] bf16
__device__ float g_bf[NFUS];                        // fused bias (fp32)
__device__ __nv_bfloat16 g_Wout_h[CH * CH];         // W_out bf16
__device__ __nv_bfloat16 g_W1_h[CH * DFFN];         // W1 bf16
__device__ __nv_bfloat16 g_W2_h[DFFN * CH];         // W2 bf16
__device__ float g_fused[NQ * NFUS];                // fused offsets + attn logits
__device__ __nv_bfloat16 g_aggh[NQ * CH];           // aggregated samples (bf16)
__device__ float g_proj[NQ * CH];                   // agg @ W_out
__device__ float g_x[NQ * CH];                      // after LN1 (fp32)
__device__ __nv_bfloat16 g_x_h[NQ * CH];            // after LN1 (bf16)
__device__ __nv_bfloat16 g_ffn1h[NQ * DFFN];        // relu(x@W1+b1) (bf16)
__device__ float g_ffn2[NQ * CH];                   // ffn1@W2+b2
__device__ unsigned int g_vis[NQ];                  // camera visibility bitmask
__device__ float g_cnt[NQ];                         // number of visible cameras

__constant__ int c_W[4] = {100, 50, 25, 13};
__constant__ int c_H[4] = {60, 30, 15, 8};
__constant__ int c_S[4] = {0, 6000, 7500, 7875};

// ---------------- f32x2 packed-math helpers ----------------
__device__ __forceinline__ u64 pkf2(float lo, float hi) {
    u64 r; asm("mov.b64 %0, {%1, %2};" : "=l"(r) : "f"(lo), "f"(hi)); return r;
}
__device__ __forceinline__ u64 bf2f2(uint32_t v) {
    uint32_t lo = v << 16, hi = v & 0xFFFF0000u;
    u64 r; asm("mov.b64 %0, {%1, %2};" : "=l"(r) : "r"(lo), "r"(hi)); return r;
}
__device__ __forceinline__ void ffma2(u64& d, u64 a, u64 b) {
    asm("fma.rn.f32x2 %0, %1, %2, %0;" : "+l"(d) : "l"(a), "l"(b));
}
__device__ __forceinline__ float2 upk(u64 v) {
    float2 f; asm("mov.b64 {%0, %1}, %2;" : "=f"(f.x), "=f"(f.y) : "l"(v)); return f;
}

// ---------------- fused prep: mask + query/weight fp32->bf16 ----------------
__global__ __launch_bounds__(256) void prep_kernel(
    const int* __restrict__ bev, const float* __restrict__ query,
    const float* __restrict__ Woff, const float* __restrict__ Wattn,
    const float* __restrict__ boff, const float* __restrict__ battn,
    const float* __restrict__ Wout, const float* __restrict__ W1,
    const float* __restrict__ W2)
{
    const int b = blockIdx.x, tid = threadIdx.x;
    if (b < 25) {
        int n = b * 256 + tid;
        unsigned int vm = 0; int cnt = 0;
        #pragma unroll
        for (int k = 0; k < CAMS; k++) {
            const int* bp = bev + ((size_t)k * NQ + n) * 4;
            if (bp[0] + bp[1] + bp[2] + bp[3] > 0) { vm |= (1u << k); cnt++; }
        }
        g_vis[n] = vm;
        g_cnt[n] = (float)cnt;
    } else if (b < 1625) {
        int i = (b - 25) * 256 + tid;           // float4 index, < 409600
        float4 v = ((const float4*)query)[i];
        ((__nv_bfloat162*)g_q_h)[i * 2]     = __floats2bfloat162_rn(v.x, v.y);
        ((__nv_bfloat162*)g_q_h)[i * 2 + 1] = __floats2bfloat162_rn(v.z, v.w);
    } else if (b < 2009) {
        int i = (b - 1625) * 256 + tid;         // < 98304
        int k = i / NFUS, n = i % NFUS;
        float v = (n < 256) ? Woff[k * 256 + n] : Wattn[k * 128 + (n - 256)];
        g_Wf_h[i] = __float2bfloat16_rn(v);
        if (i < NFUS) g_bf[i] = (i < 256) ? boff[i] : battn[i - 256];
    } else if (b < 2073) {
        int i = (b - 2009) * 256 + tid;         // < 16384
        float4 v = ((const float4*)Wout)[i];
        ((__nv_bfloat162*)g_Wout_h)[i * 2]     = __floats2bfloat162_rn(v.x, v.y);
        ((__nv_bfloat162*)g_Wout_h)[i * 2 + 1] = __floats2bfloat162_rn(v.z, v.w);
    } else if (b < 2329) {
        int i = (b - 2073) * 256 + tid;         // < 65536
        float4 v = ((const float4*)W1)[i];
        ((__nv_bfloat162*)g_W1_h)[i * 2]     = __floats2bfloat162_rn(v.x, v.y);
        ((__nv_bfloat162*)g_W1_h)[i * 2 + 1] = __floats2bfloat162_rn(v.z, v.w);
    } else {
        int i = (b - 2329) * 256 + tid;         // < 65536
        float4 v = ((const float4*)W2)[i];
        ((__nv_bfloat162*)g_W2_h)[i * 2]     = __floats2bfloat162_rn(v.x, v.y);
        ((__nv_bfloat162*)g_W2_h)[i * 2 + 1] = __floats2bfloat162_rn(v.z, v.w);
    }
}

// ---------------- value + W_value fp32 -> bf16 (stream 2) ----------------
__global__ __launch_bounds__(256) void conv_val_kernel(
    const float* __restrict__ val, const float* __restrict__ Wv)
{
    const int NV = MVAL * CH / 4;   // 3,063,936
    int i = blockIdx.x * 256 + threadIdx.x;
    if (i < NV) {
        float4 v = ((const float4*)val)[i];
        ((__nv_bfloat162*)g_val_h)[i * 2]     = __floats2bfloat162_rn(v.x, v.y);
        ((__nv_bfloat162*)g_val_h)[i * 2 + 1] = __floats2bfloat162_rn(v.z, v.w);
    } else {
        int j = i - NV;
        if (j < CH * CH / 4) {
            float4 v = ((const float4*)Wv)[j];
            ((__nv_bfloat162*)g_Wval_h)[j * 2]     = __floats2bfloat162_rn(v.x, v.y);
            ((__nv_bfloat162*)g_Wval_h)[j * 2 + 1] = __floats2bfloat162_rn(v.z, v.w);
        }
    }
}

// ---------------- tensor-core GEMM building blocks ----------------
__device__ __forceinline__ void ldsm4(uint32_t* r, const void* p) {
    uint32_t a = (uint32_t)__cvta_generic_to_shared(p);
    asm volatile("ldmatrix.sync.aligned.m8n8.x4.shared.b16 {%0,%1,%2,%3}, [%4];"
                 : "=r"(r[0]), "=r"(r[1]), "=r"(r[2]), "=r"(r[3]) : "r"(a));
}
__device__ __forceinline__ void ldsm4t(uint32_t* r, const void* p) {
    uint32_t a = (uint32_t)__cvta_generic_to_shared(p);
    asm volatile("ldmatrix.sync.aligned.m8n8.x4.trans.shared.b16 {%0,%1,%2,%3}, [%4];"
                 : "=r"(r[0]), "=r"(r[1]), "=r"(r[2]), "=r"(r[3]) : "r"(a));
}
__device__ __forceinline__ void mma_bf16(float* d, const uint32_t* a, const uint32_t* b) {
    asm volatile("mma.sync.aligned.m16n8k16.row.col.f32.bf16.bf16.f32 "
                 "{%0,%1,%2,%3}, {%4,%5,%6,%7}, {%8,%9}, {%0,%1,%2,%3};"
                 : "+f"(d[0]), "+f"(d[1]), "+f"(d[2]), "+f"(d[3])
                 : "r"(a[0]), "r"(a[1]), "r"(a[2]), "r"(a[3]), "r"(b[0]), "r"(b[1]));
}
__device__ __forceinline__ void cpa16(void* dst, const void* src) {
    uint32_t d = (uint32_t)__cvta_generic_to_shared(dst);
    asm volatile("cp.async.cg.shared.global [%0], [%1], 16;" :: "r"(d), "l"(src));
}
__device__ __forceinline__ void store2(float* C, float x, float y) {
    *(float2*)C = make_float2(x, y);
}
__device__ __forceinline__ void store2(__nv_bfloat16* C, float x, float y) {
    *(__nv_bfloat162*)C = __floats2bfloat162_rn(x, y);
}

// ================== bf16 cp.async GEMM ==================
// C(MxN) = A(MxK,bf16 rm) * B(KxN,bf16 rm) (+bias)(+relu). 128x64 tile, BK=32,
// 4-stage cp.async, 256 thr (8 warps x 32x32). M%128==0, N%64==0, K%32==0.
#define STAGES 4
template<int EPI, typename OutT>
__global__ __launch_bounds__(256, 2) void hgemm_bf16(
    const __nv_bfloat16* __restrict__ A, const __nv_bfloat16* __restrict__ B,
    const float* __restrict__ bias, OutT* __restrict__ C,
    int M, int N, int K)
{
    __shared__ __align__(16) __nv_bfloat16 As[STAGES][128][40];
    __shared__ __align__(16) __nv_bfloat16 Bs[STAGES][32][72];   // [k][n]
    const int tid = threadIdx.x;
    const int bm = blockIdx.x * 128, bn = blockIdx.y * 64;
    const int lane = tid & 31, w = tid >> 5;
    const int m0 = (w >> 1) * 32, n0 = (w & 1) * 32;

    float acc[2][4][4];
    #pragma unroll
    for (int i = 0; i < 2; i++)
        #pragma unroll
        for (int j = 0; j < 4; j++)
            #pragma unroll
            for (int l = 0; l < 4; l++) acc[i][j][l] = 0.0f;

    const int arow = tid >> 1, acol = (tid & 1) * 16;
    const int brow = tid >> 3, bcol = (tid & 7) * 8;

    const __nv_bfloat16* Asrc = A + (size_t)(bm + arow) * K + acol;
    const __nv_bfloat16* Bsrc = B + bn + bcol;

    const int KT = K >> 5;

#define ISSUE(s, kt) do {                                                      \
    cpa16(&As[s][arow][acol],     Asrc + (kt) * 32);                           \
    cpa16(&As[s][arow][acol + 8], Asrc + (kt) * 32 + 8);                       \
    cpa16(&Bs[s][brow][bcol],     Bsrc + (size_t)((kt) * 32 + brow) * N);      \
} while (0)

#define COMPUTE_T(b) do {                                                      \
    _Pragma("unroll")                                                          \
    for (int ks = 0; ks < 2; ks++) {                                           \
        uint32_t af[2][4], bfr[4][2];                                          \
        _Pragma("unroll")                                                      \
        for (int mt = 0; mt < 2; mt++)                                         \
            ldsm4(af[mt], &As[b][m0 + mt * 16 + (lane & 15)]                   \
                             [ks * 16 + ((lane >> 4) << 3)]);                  \
        _Pragma("unroll")                                                      \
        for (int nt2 = 0; nt2 < 2; nt2++) {                                    \
            uint32_t t[4];                                                     \
            ldsm4t(t, &Bs[b][ks * 16 + (lane & 7) + 8 * ((lane >> 3) & 1)]     \
                            [n0 + nt2 * 16 + 8 * (lane >> 4)]);                \
            bfr[nt2 * 2][0] = t[0];      bfr[nt2 * 2][1] = t[1];               \
            bfr[nt2 * 2 + 1][0] = t[2];  bfr[nt2 * 2 + 1][1] = t[3];           \
        }                                                                      \
        _Pragma("unroll")                                                      \
        for (int mt = 0; mt < 2; mt++)                                         \
            _Pragma("unroll")                                                  \
            for (int nt = 0; nt < 4; nt++)                                     \
                mma_bf16(acc[mt][nt], af[mt], bfr[nt]);                        \
    }                                                                          \
} while (0)

    #pragma unroll
    for (int s = 0; s < STAGES - 1; s++) {
        if (s < KT) ISSUE(s, s);
        asm volatile("cp.async.commit_group;");
    }

    for (int kt = 0; kt < KT; kt++) {
        asm volatile("cp.async.wait_group %0;" :: "n"(STAGES - 2));
        __syncthreads();
        int kn = kt + STAGES - 1;
        if (kn < KT) ISSUE(kn & (STAGES - 1), kn);
        asm volatile("cp.async.commit_group;");
        COMPUTE_T(kt & (STAGES - 1));
    }
#undef ISSUE
#undef COMPUTE_T

    const int row0 = bm + m0 + (lane >> 2);
    #pragma unroll
    for (int mt = 0; mt < 2; mt++) {
        int r0 = row0 + mt * 16, r1 = r0 + 8;
        #pragma unroll
        for (int nt = 0; nt < 4; nt++) {
            int col = bn + n0 + nt * 8 + ((lane & 3) << 1);
            float b0 = 0.f, b1 = 0.f;
            if (EPI >= 1) { b0 = __ldg(bias + col); b1 = __ldg(bias + col + 1); }
            float v0 = acc[mt][nt][0] + b0, v1 = acc[mt][nt][1] + b1;
            float v2 = acc[mt][nt][2] + b0, v3 = acc[mt][nt][3] + b1;
            if (EPI == 2) {
                v0 = fmaxf(v0, 0.f); v1 = fmaxf(v1, 0.f);
                v2 = fmaxf(v2, 0.f); v3 = fmaxf(v3, 0.f);
            }
            store2(C + (size_t)r0 * N + col, v0, v1);
            store2(C + (size_t)r1 * N + col, v2, v3);
        }
    }
}

// ---------------- deformable sampling + cross-camera aggregation ----------------
// Block = one query. Phase 0: fused 16-wide softmax. Phase 1: 768 combos ->
// weights float4 + absolute corner row-indices int4 in smem. Phase 2: thread
// (cg = tid&31 -> 8 channels, pgrp = tid>>5 -> 2 of 16 points) gathers uint4
// (8 bf16) per corner, packed f32x2 FMA. 3-round smem reduction over pgrp.
__global__ __launch_bounds__(256) void sample_kernel(
    const float* __restrict__ ref)   // (6, 6400, 4, 2)
{
    __shared__ float4 sw[768];
    __shared__ int4 sidx[768];
    __shared__ float saw[128];
    __shared__ float4 sred[256][2];
    const int n = blockIdx.x;
    const int tid = threadIdx.x;
    const unsigned int vism = g_vis[n];

    // Phase 0: softmax over each 16-point group (8 heads)
    if (tid < 128) {
        float lv = g_fused[(size_t)n * NFUS + 256 + tid];
        float mx = lv;
        #pragma unroll
        for (int o = 8; o > 0; o >>= 1)
            mx = fmaxf(mx, __shfl_xor_sync(0xffffffffu, mx, o));
        float e = expf(lv - mx);
        float s = e;
        #pragma unroll
        for (int o = 8; o > 0; o >>= 1)
            s += __shfl_xor_sync(0xffffffffu, s, o);
        saw[tid] = e / s;
    }
    __syncthreads();

    // Phase 1: weights + corner row indices
    #pragma unroll
    for (int t = 0; t < 3; t++) {
        int cid = tid + t * 256;
        int k = cid >> 7;
        int r = cid & 127;          // h*16 + lvl*4 + p
        int h = r >> 4;
        int lvl = (r >> 2) & 3;
        int p = r & 3;
        float4 wv = make_float4(0.f, 0.f, 0.f, 0.f);
        int4 iv = make_int4(0, 0, 0, 0);
        if ((vism >> k) & 1) {
            int Wi = c_W[lvl], Hi = c_H[lvl];
            float Wf = (float)Wi, Hf = (float)Hi;
            const float* rp = ref + (((size_t)k * NQ + n) * 4 + lvl) * 2;
            float rx = rp[0], ry = rp[1];
            int oi = ((h * 4 + lvl) * 4 + p) * 2;
            float ox = g_fused[(size_t)n * NFUS + oi];
            float oy = g_fused[(size_t)n * NFUS + oi + 1];
            float x = (rx + ox / Wf) * Wf - 0.5f;
            float y = (ry + oy / Hf) * Hf - 0.5f;
            float x0f = floorf(x), y0f = floorf(y);
            float lx = x - x0f, ly = y - y0f;
            int x0 = (int)x0f, y0 = (int)y0f;
            float a = saw[r];
            bool vx0 = (x0 >= 0) && (x0 < Wi);
            bool vx1 = (x0 + 1 >= 0) && (x0 + 1 < Wi);
            bool vy0 = (y0 >= 0) && (y0 < Hi);
            bool vy1 = (y0 + 1 >= 0) && (y0 + 1 < Hi);
            float omx = 1.0f - lx, omy = 1.0f - ly;
            wv.x = (vx0 && vy0) ? a * omx * omy : 0.0f;
            wv.y = (vx1 && vy0) ? a * lx * omy : 0.0f;
            wv.z = (vx0 && vy1) ? a * omx * ly : 0.0f;
            wv.w = (vx1 && vy1) ? a * lx * ly : 0.0f;
            int xc0 = min(max(x0, 0), Wi - 1);
            int xc1 = min(max(x0 + 1, 0), Wi - 1);
            int yc0 = min(max(y0, 0), Hi - 1);
            int yc1 = min(max(y0 + 1, 0), Hi - 1);
            int rb = k * LTOT + c_S[lvl];
            int r0 = rb + yc0 * Wi, r1 = rb + yc1 * Wi;
            iv = make_int4(r0 + xc0, r0 + xc1, r1 + xc0, r1 + xc1);
        }
        sw[cid] = wv;
        sidx[cid] = iv;
    }
    __syncthreads();

    // Phase 2: gather + packed FMA
    const int cg = tid & 31;              // 8-channel group
    const int hh = cg >> 2;               // head
    const int pgrp = tid >> 5;            // handles points {2*pgrp, 2*pgrp+1}
    const __nv_bfloat16* vb = g_vproj + cg * 8;
    u64 a0 = 0, a1 = 0, a2 = 0, a3 = 0;

    #pragma unroll 1
    for (int k = 0; k < CAMS; k++) {
        if (!((vism >> k) & 1)) continue;
        const int base = k * 128 + hh * 16 + pgrp * 2;
        #pragma unroll
        for (int j = 0; j < 2; j++) {
            float4 w = sw[base + j];
            int4 iv = sidx[base + j];
            u64 w0 = pkf2(w.x, w.x), w1 = pkf2(w.y, w.y);
            u64 w2 = pkf2(w.z, w.z), w3 = pkf2(w.w, w.w);
            uint4 q0 = *(const uint4*)(vb + ((size_t)iv.x << 8));
            uint4 q1 = *(const uint4*)(vb + ((size_t)iv.y << 8));
            uint4 q2 = *(const uint4*)(vb + ((size_t)iv.z << 8));
            uint4 q3 = *(const uint4*)(vb + ((size_t)iv.w << 8));
            ffma2(a0, w0, bf2f2(q0.x)); ffma2(a1, w0, bf2f2(q0.y));
            ffma2(a2, w0, bf2f2(q0.z)); ffma2(a3, w0, bf2f2(q0.w));
            ffma2(a0, w1, bf2f2(q1.x)); ffma2(a1, w1, bf2f2(q1.y));
            ffma2(a2, w1, bf2f2(q1.z)); ffma2(a3, w1, bf2f2(q1.w));
            ffma2(a0, w2, bf2f2(q2.x)); ffma2(a1, w2, bf2f2(q2.y));
            ffma2(a2, w2, bf2f2(q2.z)); ffma2(a3, w2, bf2f2(q2.w));
            ffma2(a0, w3, bf2f2(q3.x)); ffma2(a1, w3, bf2f2(q3.y));
            ffma2(a2, w3, bf2f2(q3.z)); ffma2(a3, w3, bf2f2(q3.w));
        }
    }

    float2 f0 = upk(a0), f1 = upk(a1), f2 = upk(a2), f3 = upk(a3);
    sred[tid][0] = make_float4(f0.x, f0.y, f1.x, f1.y);
    sred[tid][1] = make_float4(f2.x, f2.y, f3.x, f3.y);
    __syncthreads();
    if (tid < 128) {
        float4 x0 = sred[tid + 128][0], x1 = sred[tid + 128][1];
        float4 y0 = sred[tid][0], y1 = sred[tid][1];
        y0.x += x0.x; y0.y += x0.y; y0.z += x0.z; y0.w += x0.w;
        y1.x += x1.x; y1.y += x1.y; y1.z += x1.z; y1.w += x1.w;
        sred[tid][0] = y0; sred[tid][1] = y1;
    }
    __syncthreads();
    if (tid < 64) {
        float4 x0 = sred[tid + 64][0], x1 = sred[tid + 64][1];
        float4 y0 = sred[tid][0], y1 = sred[tid][1];
        y0.x += x0.x; y0.y += x0.y; y0.z += x0.z; y0.w += x0.w;
        y1.x += x1.x; y1.y += x1.y; y1.z += x1.z; y1.w += x1.w;
        sred[tid][0] = y0; sred[tid][1] = y1;
    }
    __syncthreads();
    if (tid < 32) {
        float4 x0 = sred[tid + 32][0], x1 = sred[tid + 32][1];
        float4 y0 = sred[tid][0], y1 = sred[tid][1];
        y0.x += x0.x; y0.y += x0.y; y0.z += x0.z; y0.w += x0.w;
        y1.x += x1.x; y1.y += x1.y; y1.z += x1.z; y1.w += x1.w;
        __nv_bfloat162 p0 = __floats2bfloat162_rn(y0.x, y0.y);
        __nv_bfloat162 p1 = __floats2bfloat162_rn(y0.z, y0.w);
        __nv_bfloat162 p2 = __floats2bfloat162_rn(y1.x, y1.y);
        __nv_bfloat162 p3 = __floats2bfloat162_rn(y1.z, y1.w);
        uint4 pk;
        pk.x = *(uint32_t*)&p0; pk.y = *(uint32_t*)&p1;
        pk.z = *(uint32_t*)&p2; pk.w = *(uint32_t*)&p3;
        *(uint4*)(g_aggh + (size_t)n * CH + tid * 8) = pk;
    }
}

// ---------------- block reduction helper ----------------
__device__ __forceinline__ float blocksum256(float v, float* sh) {
    #pragma unroll
    for (int o = 16; o > 0; o >>= 1) v += __shfl_xor_sync(0xffffffffu, v, o);
    if ((threadIdx.x & 31) == 0) sh[threadIdx.x >> 5] = v;
    __syncthreads();
    float s = 0.f;
    #pragma unroll
    for (int i = 0; i < 8; i++) s += sh[i];
    __syncthreads();
    return s;
}

// ---------------- slots assembly + residual + LN1 ----------------
__global__ __launch_bounds__(256) void ln1_kernel(
    const float* __restrict__ query, const float* __restrict__ b_out,
    const float* __restrict__ gamma, const float* __restrict__ beta)
{
    __shared__ float sh[8];
    const int n = blockIdx.x, c = threadIdx.x;
    float m = g_cnt[n];
    float q = query[(size_t)n * CH + c];
    float s = m * (q + b_out[c]) + g_proj[(size_t)n * CH + c];
    float t = s / fmaxf(m, 1.0f) + q;
    float mu = blocksum256(t, sh) * (1.0f / CH);
    float d = t - mu;
    float var = blocksum256(d * d, sh) * (1.0f / CH);
    float xv = d * rsqrtf(var + 1e-5f) * gamma[c] + beta[c];
    g_x[(size_t)n * CH + c] = xv;
    g_x_h[(size_t)n * CH + c] = __float2bfloat16_rn(xv);
}

// ---------------- FFN residual + LN2 -> output ----------------
__global__ __launch_bounds__(256) void ln2_kernel(
    const float* __restrict__ gamma, const float* __restrict__ beta,
    float* __restrict__ out)
{
    __shared__ float sh[8];
    const int n = blockIdx.x, c = threadIdx.x;
    float t = g_x[(size_t)n * CH + c] + g_ffn2[(size_t)n * CH + c];
    float mu = blocksum256(t, sh) * (1.0f / CH);
    float d = t - mu;
    float var = blocksum256(d * d, sh) * (1.0f / CH);
    out[(size_t)n * CH + c] = d * rsqrtf(var + 1e-5f) * gamma[c] + beta[c];
}

// ---------------- host launcher ----------------
extern "C" void kernel_launch(void* const* d_in, const int* in_sizes, int n_in,
                              void* d_out, int out_size) {
    const float* query   = (const float*)d_in[0];
    const float* value   = (const float*)d_in[2];
    const float* refpts  = (const float*)d_in[3];
    const int*   bev     = (const int*)d_in[6];
    const float* W_value = (const float*)d_in[7];
    const float* b_value = (const float*)d_in[8];
    const float* W_off   = (const float*)d_in[9];
    const float* b_off   = (const float*)d_in[10];
    const float* W_attn  = (const float*)d_in[11];
    const float* b_attn  = (const float*)d_in[12];
    const float* W_out   = (const float*)d_in[13];
    const float* b_out   = (const float*)d_in[14];
    const float* ln1_g   = (const float*)d_in[15];
    const float* ln1_b   = (const float*)d_in[16];
    const float* W1      = (const float*)d_in[17];
    const float* b1      = (const float*)d_in[18];
    const float* W2      = (const float*)d_in[19];
    const float* b2      = (const float*)d_in[20];
    const float* ln2_g   = (const float*)d_in[21];
    const float* ln2_b   = (const float*)d_in[22];
    float* out = (float*)d_out;

    void *p_valh, *p_Wvalh, *p_vproj, *p_qh, *p_Wfh, *p_bf, *p_Wouth, *p_W1h, *p_W2h;
    void *p_fused, *p_aggh, *p_proj, *p_xh, *p_ffn1h, *p_ffn2;
    cudaGetSymbolAddress(&p_valh,   g_val_h);
    cudaGetSymbolAddress(&p_Wvalh,  g_Wval_h);
    cudaGetSymbolAddress(&p_vproj,  g_vproj);
    cudaGetSymbolAddress(&p_qh,     g_q_h);
    cudaGetSymbolAddress(&p_Wfh,    g_Wf_h);
    cudaGetSymbolAddress(&p_bf,     g_bf);
    cudaGetSymbolAddress(&p_Wouth,  g_Wout_h);
    cudaGetSymbolAddress(&p_W1h,    g_W1_h);
    cudaGetSymbolAddress(&p_W2h,    g_W2_h);
    cudaGetSymbolAddress(&p_fused,  g_fused);
    cudaGetSymbolAddress(&p_aggh,   g_aggh);
    cudaGetSymbolAddress(&p_proj,   g_proj);
    cudaGetSymbolAddress(&p_xh,     g_x_h);
    cudaGetSymbolAddress(&p_ffn1h,  g_ffn1h);
    cudaGetSymbolAddress(&p_ffn2,   g_ffn2);

    static cudaStream_t s2 = nullptr;
    static cudaEvent_t ev_fork = nullptr, ev_join = nullptr;
    if (s2 == nullptr) {
        cudaStreamCreateWithFlags(&s2, cudaStreamNonBlocking);
        cudaEventCreateWithFlags(&ev_fork, cudaEventDisableTiming);
        cudaEventCreateWithFlags(&ev_join, cudaEventDisableTiming);
    }

    // ---- fork: value/W_value conversion + vproj GEMM on s2 ----
    cudaEventRecord(ev_fork, 0);
    cudaStreamWaitEvent(s2, ev_fork, 0);
    {
        int nconv = (MVAL * CH / 4 + CH * CH / 4 + 255) / 256;
        conv_val_kernel<<<nconv, 256, 0, s2>>>(value, W_value);
        hgemm_bf16<1, __nv_bfloat16><<<dim3(MPAD / 128, CH / 64), 256, 0, s2>>>(
            (const __nv_bfloat16*)p_valh, (const __nv_bfloat16*)p_Wvalh,
            b_value, (__nv_bfloat16*)p_vproj, MPAD, CH, CH);
    }
    cudaEventRecord(ev_join, s2);

    // ---- main stream: prep + fused off/attn GEMM ----
    prep_kernel<<<2585, 256>>>(bev, query, W_off, W_attn, b_off, b_attn,
                               W_out, W1, W2);
    hgemm_bf16<1, float><<<dim3(NQ / 128, NFUS / 64), 256>>>(
        (const __nv_bfloat16*)p_qh, (const __nv_bfloat16*)p_Wfh,
        (const float*)p_bf, (float*)p_fused, NQ, NFUS, CH);

    // ---- join, then sampling ----
    cudaStreamWaitEvent(0, ev_join, 0);
    sample_kernel<<<NQ, 256>>>(refpts);

    // output projection: agg(bf16) @ W_out (bias folded into ln1)
    hgemm_bf16<0, float><<<dim3(NQ / 128, CH / 64), 256>>>(
        (const __nv_bfloat16*)p_aggh, (const __nv_bfloat16*)p_Wouth,
        nullptr, (float*)p_proj, NQ, CH, CH);

    // slots + residual + LN1
    ln1_kernel<<<NQ, 256>>>(query, b_out, ln1_g, ln1_b);

    // FFN up: relu(x @ W1 + b1) -> bf16
    hgemm_bf16<2, __nv_bfloat16><<<dim3(NQ / 128, DFFN / 64), 256>>>(
        (const __nv_bfloat16*)p_xh, (const __nv_bfloat16*)p_W1h,
        b1, (__nv_bfloat16*)p_ffn1h, NQ, DFFN, CH);

    // FFN down: ffn1(bf16) @ W2 + b2
    hgemm_bf16<1, float><<<dim3(NQ / 128, CH / 64), 256>>>(
        (const __nv_bfloat16*)p_ffn1h, (const __nv_bfloat16*)p_W2h,
        b2, (float*)p_ffn2, NQ, CH, DFFN);

    // residual + LN2 -> out
    ln2_kernel<<<NQ, 256>>>(ln2_g, ln2_b, out);

    (void)in_sizes; (void)n_in; (void)out_size;
}

// round 8
// speedup vs baseline: 3.1042x; 1.0162x over previous
#include <cuda_runtime.h>
#include <cuda_bf16.h>
#include <stdint.h>

// Problem constants (fixed by setup_inputs)
#define NQ   6400
#define CAMS 6
#define LTOT 7979
#define CH   256
#define DFFN 1024
#define NFUS 384   // fused off(256) + attn-logits(128)
#define MVAL (CAMS * LTOT)   // 47874
#define MPAD 48000           // 375 * 128

typedef unsigned long long u64;

// ---------------- scratch (static device globals; no allocation) ----------------
__device__ __nv_bfloat16 g_val_h[MPAD * CH];        // value in bf16 (padded rows stay 0)
__device__ __nv_bfloat16 g_Wval_h[CH * CH];         // W_value bf16
__device__ __nv_bfloat16 g_vproj[MPAD * CH];        // value @ W_value + b (bf16)
__device__ __nv_bfloat16 g_q_h[NQ * CH];            // query in bf16
__device__ __nv_bfloat16 g_Wf_h[CH * NFUS];         // fused [W_off | W_attn] bf16
__device__ float g_bf[NFUS];                        // fused bias (fp32)
__device__ __nv_bfloat16 g_Wout_h[CH * CH];         // W_out bf16
__device__ __nv_bfloat16 g_W1_h[CH * DFFN];         // W1 bf16
__device__ __nv_bfloat16 g_W2_h[DFFN * CH];         // W2 bf16
__device__ float g_fused[NQ * NFUS];                // fused offsets + attn logits
__device__ __nv_bfloat16 g_aggh[NQ * CH];           // aggregated samples (bf16)
__device__ float g_proj[NQ * CH];                   // agg @ W_out
__device__ float g_x[NQ * CH];                      // after LN1 (fp32)
__device__ __nv_bfloat16 g_x_h[NQ * CH];            // after LN1 (bf16)
__device__ __nv_bfloat16 g_ffn1h[NQ * DFFN];        // relu(x@W1+b1) (bf16)
__device__ float g_ffn2[NQ * CH];                   // ffn1@W2+b2
__device__ unsigned int g_vis[NQ];                  // camera visibility bitmask
__device__ float g_cnt[NQ];                         // number of visible cameras

__constant__ int c_W[4] = {100, 50, 25, 13};
__constant__ int c_H[4] = {60, 30, 15, 8};
__constant__ int c_S[4] = {0, 6000, 7500, 7875};

// ---------------- f32x2 packed-math helpers ----------------
__device__ __forceinline__ u64 pkf2(float lo, float hi) {
    u64 r; asm("mov.b64 %0, {%1, %2};" : "=l"(r) : "f"(lo), "f"(hi)); return r;
}
__device__ __forceinline__ u64 bf2f2(uint32_t v) {
    uint32_t lo = v << 16, hi = v & 0xFFFF0000u;
    u64 r; asm("mov.b64 %0, {%1, %2};" : "=l"(r) : "r"(lo), "r"(hi)); return r;
}
__device__ __forceinline__ void ffma2(u64& d, u64 a, u64 b) {
    asm("fma.rn.f32x2 %0, %1, %2, %0;" : "+l"(d) : "l"(a), "l"(b));
}
__device__ __forceinline__ float2 upk(u64 v) {
    float2 f; asm("mov.b64 {%0, %1}, %2;" : "=f"(f.x), "=f"(f.y) : "l"(v)); return f;
}

// ---------------- fused prep: mask + query/weight fp32->bf16 ----------------
__global__ __launch_bounds__(256) void prep_kernel(
    const int* __restrict__ bev, const float* __restrict__ query,
    const float* __restrict__ Woff, const float* __restrict__ Wattn,
    const float* __restrict__ boff, const float* __restrict__ battn,
    const float* __restrict__ Wout, const float* __restrict__ W1,
    const float* __restrict__ W2)
{
    const int b = blockIdx.x, tid = threadIdx.x;
    if (b < 25) {
        int n = b * 256 + tid;
        unsigned int vm = 0; int cnt = 0;
        #pragma unroll
        for (int k = 0; k < CAMS; k++) {
            const int* bp = bev + ((size_t)k * NQ + n) * 4;
            if (bp[0] + bp[1] + bp[2] + bp[3] > 0) { vm |= (1u << k); cnt++; }
        }
        g_vis[n] = vm;
        g_cnt[n] = (float)cnt;
    } else if (b < 1625) {
        int i = (b - 25) * 256 + tid;           // float4 index, < 409600
        float4 v = ((const float4*)query)[i];
        ((__nv_bfloat162*)g_q_h)[i * 2]     = __floats2bfloat162_rn(v.x, v.y);
        ((__nv_bfloat162*)g_q_h)[i * 2 + 1] = __floats2bfloat162_rn(v.z, v.w);
    } else if (b < 2009) {
        int i = (b - 1625) * 256 + tid;         // < 98304
        int k = i / NFUS, n = i % NFUS;
        float v = (n < 256) ? Woff[k * 256 + n] : Wattn[k * 128 + (n - 256)];
        g_Wf_h[i] = __float2bfloat16_rn(v);
        if (i < NFUS) g_bf[i] = (i < 256) ? boff[i] : battn[i - 256];
    } else if (b < 2073) {
        int i = (b - 2009) * 256 + tid;         // < 16384
        float4 v = ((const float4*)Wout)[i];
        ((__nv_bfloat162*)g_Wout_h)[i * 2]     = __floats2bfloat162_rn(v.x, v.y);
        ((__nv_bfloat162*)g_Wout_h)[i * 2 + 1] = __floats2bfloat162_rn(v.z, v.w);
    } else if (b < 2329) {
        int i = (b - 2073) * 256 + tid;         // < 65536
        float4 v = ((const float4*)W1)[i];
        ((__nv_bfloat162*)g_W1_h)[i * 2]     = __floats2bfloat162_rn(v.x, v.y);
        ((__nv_bfloat162*)g_W1_h)[i * 2 + 1] = __floats2bfloat162_rn(v.z, v.w);
    } else {
        int i = (b - 2329) * 256 + tid;         // < 65536
        float4 v = ((const float4*)W2)[i];
        ((__nv_bfloat162*)g_W2_h)[i * 2]     = __floats2bfloat162_rn(v.x, v.y);
        ((__nv_bfloat162*)g_W2_h)[i * 2 + 1] = __floats2bfloat162_rn(v.z, v.w);
    }
}

// ---------------- value + W_value fp32 -> bf16 (stream 2) ----------------
__global__ __launch_bounds__(256) void conv_val_kernel(
    const float* __restrict__ val, const float* __restrict__ Wv)
{
    const int NV = MVAL * CH / 4;   // 3,063,936
    int i = blockIdx.x * 256 + threadIdx.x;
    if (i < NV) {
        float4 v = ((const float4*)val)[i];
        ((__nv_bfloat162*)g_val_h)[i * 2]     = __floats2bfloat162_rn(v.x, v.y);
        ((__nv_bfloat162*)g_val_h)[i * 2 + 1] = __floats2bfloat162_rn(v.z, v.w);
    } else {
        int j = i - NV;
        if (j < CH * CH / 4) {
            float4 v = ((const float4*)Wv)[j];
            ((__nv_bfloat162*)g_Wval_h)[j * 2]     = __floats2bfloat162_rn(v.x, v.y);
            ((__nv_bfloat162*)g_Wval_h)[j * 2 + 1] = __floats2bfloat162_rn(v.z, v.w);
        }
    }
}

// ---------------- tensor-core GEMM building blocks ----------------
__device__ __forceinline__ void ldsm4(uint32_t* r, const void* p) {
    uint32_t a = (uint32_t)__cvta_generic_to_shared(p);
    asm volatile("ldmatrix.sync.aligned.m8n8.x4.shared.b16 {%0,%1,%2,%3}, [%4];"
                 : "=r"(r[0]), "=r"(r[1]), "=r"(r[2]), "=r"(r[3]) : "r"(a));
}
__device__ __forceinline__ void ldsm4t(uint32_t* r, const void* p) {
    uint32_t a = (uint32_t)__cvta_generic_to_shared(p);
    asm volatile("ldmatrix.sync.aligned.m8n8.x4.trans.shared.b16 {%0,%1,%2,%3}, [%4];"
                 : "=r"(r[0]), "=r"(r[1]), "=r"(r[2]), "=r"(r[3]) : "r"(a));
}
__device__ __forceinline__ void mma_bf16(float* d, const uint32_t* a, const uint32_t* b) {
    asm volatile("mma.sync.aligned.m16n8k16.row.col.f32.bf16.bf16.f32 "
                 "{%0,%1,%2,%3}, {%4,%5,%6,%7}, {%8,%9}, {%0,%1,%2,%3};"
                 : "+f"(d[0]), "+f"(d[1]), "+f"(d[2]), "+f"(d[3])
                 : "r"(a[0]), "r"(a[1]), "r"(a[2]), "r"(a[3]), "r"(b[0]), "r"(b[1]));
}
__device__ __forceinline__ void cpa16(void* dst, const void* src) {
    uint32_t d = (uint32_t)__cvta_generic_to_shared(dst);
    asm volatile("cp.async.cg.shared.global [%0], [%1], 16;" :: "r"(d), "l"(src));
}
__device__ __forceinline__ void store2(float* C, float x, float y) {
    *(float2*)C = make_float2(x, y);
}
__device__ __forceinline__ void store2(__nv_bfloat16* C, float x, float y) {
    *(__nv_bfloat162*)C = __floats2bfloat162_rn(x, y);
}

// ================== bf16 cp.async GEMM ==================
// C(MxN) = A(MxK,bf16 rm) * B(KxN,bf16 rm) (+bias)(+relu). 128x64 tile, BK=32,
// 4-stage cp.async, 256 thr (8 warps x 32x32), 3 CTAs/SM target.
// M%128==0, N%64==0, K%32==0. EPI: 0 none, 1 +bias, 2 +bias+relu.
#define STAGES 4
template<int EPI, typename OutT>
__global__ __launch_bounds__(256, 3) void hgemm_bf16(
    const __nv_bfloat16* __restrict__ A, const __nv_bfloat16* __restrict__ B,
    const float* __restrict__ bias, OutT* __restrict__ C,
    int M, int N, int K)
{
    __shared__ __align__(16) __nv_bfloat16 As[STAGES][128][40];
    __shared__ __align__(16) __nv_bfloat16 Bs[STAGES][32][72];   // [k][n]
    const int tid = threadIdx.x;
    const int bm = blockIdx.x * 128, bn = blockIdx.y * 64;
    const int lane = tid & 31, w = tid >> 5;
    const int m0 = (w >> 1) * 32, n0 = (w & 1) * 32;

    float acc[2][4][4];
    #pragma unroll
    for (int i = 0; i < 2; i++)
        #pragma unroll
        for (int j = 0; j < 4; j++)
            #pragma unroll
            for (int l = 0; l < 4; l++) acc[i][j][l] = 0.0f;

    const int arow = tid >> 1, acol = (tid & 1) * 16;
    const int brow = tid >> 3, bcol = (tid & 7) * 8;

    const __nv_bfloat16* Asrc = A + (size_t)(bm + arow) * K + acol;
    const __nv_bfloat16* Bsrc = B + bn + bcol;

    const int KT = K >> 5;

#define ISSUE(s, kt) do {                                                      \
    cpa16(&As[s][arow][acol],     Asrc + (kt) * 32);                           \
    cpa16(&As[s][arow][acol + 8], Asrc + (kt) * 32 + 8);                       \
    cpa16(&Bs[s][brow][bcol],     Bsrc + (size_t)((kt) * 32 + brow) * N);      \
} while (0)

#define COMPUTE_T(b) do {                                                      \
    _Pragma("unroll")                                                          \
    for (int ks = 0; ks < 2; ks++) {                                           \
        uint32_t af[2][4], bfr[4][2];                                          \
        _Pragma("unroll")                                                      \
        for (int mt = 0; mt < 2; mt++)                                         \
            ldsm4(af[mt], &As[b][m0 + mt * 16 + (lane & 15)]                   \
                             [ks * 16 + ((lane >> 4) << 3)]);                  \
        _Pragma("unroll")                                                      \
        for (int nt2 = 0; nt2 < 2; nt2++) {                                    \
            uint32_t t[4];                                                     \
            ldsm4t(t, &Bs[b][ks * 16 + (lane & 7) + 8 * ((lane >> 3) & 1)]     \
                            [n0 + nt2 * 16 + 8 * (lane >> 4)]);                \
            bfr[nt2 * 2][0] = t[0];      bfr[nt2 * 2][1] = t[1];               \
            bfr[nt2 * 2 + 1][0] = t[2];  bfr[nt2 * 2 + 1][1] = t[3];           \
        }                                                                      \
        _Pragma("unroll")                                                      \
        for (int mt = 0; mt < 2; mt++)                                         \
            _Pragma("unroll")                                                  \
            for (int nt = 0; nt < 4; nt++)                                     \
                mma_bf16(acc[mt][nt], af[mt], bfr[nt]);                        \
    }                                                                          \
} while (0)

    #pragma unroll
    for (int s = 0; s < STAGES - 1; s++) {
        if (s < KT) ISSUE(s, s);
        asm volatile("cp.async.commit_group;");
    }

    for (int kt = 0; kt < KT; kt++) {
        asm volatile("cp.async.wait_group %0;" :: "n"(STAGES - 2));
        __syncthreads();
        int kn = kt + STAGES - 1;
        if (kn < KT) ISSUE(kn & (STAGES - 1), kn);
        asm volatile("cp.async.commit_group;");
        COMPUTE_T(kt & (STAGES - 1));
    }
#undef ISSUE
#undef COMPUTE_T

    const int row0 = bm + m0 + (lane >> 2);
    #pragma unroll
    for (int mt = 0; mt < 2; mt++) {
        int r0 = row0 + mt * 16, r1 = r0 + 8;
        #pragma unroll
        for (int nt = 0; nt < 4; nt++) {
            int col = bn + n0 + nt * 8 + ((lane & 3) << 1);
            float b0 = 0.f, b1 = 0.f;
            if (EPI >= 1) { b0 = __ldg(bias + col); b1 = __ldg(bias + col + 1); }
            float v0 = acc[mt][nt][0] + b0, v1 = acc[mt][nt][1] + b1;
            float v2 = acc[mt][nt][2] + b0, v3 = acc[mt][nt][3] + b1;
            if (EPI == 2) {
                v0 = fmaxf(v0, 0.f); v1 = fmaxf(v1, 0.f);
                v2 = fmaxf(v2, 0.f); v3 = fmaxf(v3, 0.f);
            }
            store2(C + (size_t)r0 * N + col, v0, v1);
            store2(C + (size_t)r1 * N + col, v2, v3);
        }
    }
}

// ---------------- deformable sampling + cross-camera aggregation ----------------
__global__ __launch_bounds__(256) void sample_kernel(
    const float* __restrict__ ref)   // (6, 6400, 4, 2)
{
    __shared__ float4 sw[768];
    __shared__ int4 sidx[768];
    __shared__ float saw[128];
    __shared__ float4 sred[256][2];
    const int n = blockIdx.x;
    const int tid = threadIdx.x;
    const unsigned int vism = g_vis[n];

    // Phase 0: softmax over each 16-point group (8 heads)
    if (tid < 128) {
        float lv = g_fused[(size_t)n * NFUS + 256 + tid];
        float mx = lv;
        #pragma unroll
        for (int o = 8; o > 0; o >>= 1)
            mx = fmaxf(mx, __shfl_xor_sync(0xffffffffu, mx, o));
        float e = expf(lv - mx);
        float s = e;
        #pragma unroll
        for (int o = 8; o > 0; o >>= 1)
            s += __shfl_xor_sync(0xffffffffu, s, o);
        saw[tid] = e / s;
    }
    __syncthreads();

    // Phase 1: weights + corner row indices
    #pragma unroll
    for (int t = 0; t < 3; t++) {
        int cid = tid + t * 256;
        int k = cid >> 7;
        int r = cid & 127;          // h*16 + lvl*4 + p
        int h = r >> 4;
        int lvl = (r >> 2) & 3;
        int p = r & 3;
        float4 wv = make_float4(0.f, 0.f, 0.f, 0.f);
        int4 iv = make_int4(0, 0, 0, 0);
        if ((vism >> k) & 1) {
            int Wi = c_W[lvl], Hi = c_H[lvl];
            float Wf = (float)Wi, Hf = (float)Hi;
            const float* rp = ref + (((size_t)k * NQ + n) * 4 + lvl) * 2;
            float rx = rp[0], ry = rp[1];
            int oi = ((h * 4 + lvl) * 4 + p) * 2;
            float ox = g_fused[(size_t)n * NFUS + oi];
            float oy = g_fused[(size_t)n * NFUS + oi + 1];
            float x = (rx + ox / Wf) * Wf - 0.5f;
            float y = (ry + oy / Hf) * Hf - 0.5f;
            float x0f = floorf(x), y0f = floorf(y);
            float lx = x - x0f, ly = y - y0f;
            int x0 = (int)x0f, y0 = (int)y0f;
            float a = saw[r];
            bool vx0 = (x0 >= 0) && (x0 < Wi);
            bool vx1 = (x0 + 1 >= 0) && (x0 + 1 < Wi);
            bool vy0 = (y0 >= 0) && (y0 < Hi);
            bool vy1 = (y0 + 1 >= 0) && (y0 + 1 < Hi);
            float omx = 1.0f - lx, omy = 1.0f - ly;
            wv.x = (vx0 && vy0) ? a * omx * omy : 0.0f;
            wv.y = (vx1 && vy0) ? a * lx * omy : 0.0f;
            wv.z = (vx0 && vy1) ? a * omx * ly : 0.0f;
            wv.w = (vx1 && vy1) ? a * lx * ly : 0.0f;
            int xc0 = min(max(x0, 0), Wi - 1);
            int xc1 = min(max(x0 + 1, 0), Wi - 1);
            int yc0 = min(max(y0, 0), Hi - 1);
            int yc1 = min(max(y0 + 1, 0), Hi - 1);
            int rb = k * LTOT + c_S[lvl];
            int r0 = rb + yc0 * Wi, r1 = rb + yc1 * Wi;
            iv = make_int4(r0 + xc0, r0 + xc1, r1 + xc0, r1 + xc1);
        }
        sw[cid] = wv;
        sidx[cid] = iv;
    }
    __syncthreads();

    // Phase 2: gather + packed FMA
    const int cg = tid & 31;              // 8-channel group
    const int hh = cg >> 2;               // head
    const int pgrp = tid >> 5;            // handles points {2*pgrp, 2*pgrp+1}
    const __nv_bfloat16* vb = g_vproj + cg * 8;
    u64 a0 = 0, a1 = 0, a2 = 0, a3 = 0;

    #pragma unroll 1
    for (int k = 0; k < CAMS; k++) {
        if (!((vism >> k) & 1)) continue;
        const int base = k * 128 + hh * 16 + pgrp * 2;
        #pragma unroll
        for (int j = 0; j < 2; j++) {
            float4 w = sw[base + j];
            int4 iv = sidx[base + j];
            u64 w0 = pkf2(w.x, w.x), w1 = pkf2(w.y, w.y);
            u64 w2 = pkf2(w.z, w.z), w3 = pkf2(w.w, w.w);
            uint4 q0 = *(const uint4*)(vb + ((size_t)iv.x << 8));
            uint4 q1 = *(const uint4*)(vb + ((size_t)iv.y << 8));
            uint4 q2 = *(const uint4*)(vb + ((size_t)iv.z << 8));
            uint4 q3 = *(const uint4*)(vb + ((size_t)iv.w << 8));
            ffma2(a0, w0, bf2f2(q0.x)); ffma2(a1, w0, bf2f2(q0.y));
            ffma2(a2, w0, bf2f2(q0.z)); ffma2(a3, w0, bf2f2(q0.w));
            ffma2(a0, w1, bf2f2(q1.x)); ffma2(a1, w1, bf2f2(q1.y));
            ffma2(a2, w1, bf2f2(q1.z)); ffma2(a3, w1, bf2f2(q1.w));
            ffma2(a0, w2, bf2f2(q2.x)); ffma2(a1, w2, bf2f2(q2.y));
            ffma2(a2, w2, bf2f2(q2.z)); ffma2(a3, w2, bf2f2(q2.w));
            ffma2(a0, w3, bf2f2(q3.x)); ffma2(a1, w3, bf2f2(q3.y));
            ffma2(a2, w3, bf2f2(q3.z)); ffma2(a3, w3, bf2f2(q3.w));
        }
    }

    float2 f0 = upk(a0), f1 = upk(a1), f2 = upk(a2), f3 = upk(a3);
    sred[tid][0] = make_float4(f0.x, f0.y, f1.x, f1.y);
    sred[tid][1] = make_float4(f2.x, f2.y, f3.x, f3.y);
    __syncthreads();
    if (tid < 128) {
        float4 x0 = sred[tid + 128][0], x1 = sred[tid + 128][1];
        float4 y0 = sred[tid][0], y1 = sred[tid][1];
        y0.x += x0.x; y0.y += x0.y; y0.z += x0.z; y0.w += x0.w;
        y1.x += x1.x; y1.y += x1.y; y1.z += x1.z; y1.w += x1.w;
        sred[tid][0] = y0; sred[tid][1] = y1;
    }
    __syncthreads();
    if (tid < 64) {
        float4 x0 = sred[tid + 64][0], x1 = sred[tid + 64][1];
        float4 y0 = sred[tid][0], y1 = sred[tid][1];
        y0.x += x0.x; y0.y += x0.y; y0.z += x0.z; y0.w += x0.w;
        y1.x += x1.x; y1.y += x1.y; y1.z += x1.z; y1.w += x1.w;
        sred[tid][0] = y0; sred[tid][1] = y1;
    }
    __syncthreads();
    if (tid < 32) {
        float4 x0 = sred[tid + 32][0], x1 = sred[tid + 32][1];
        float4 y0 = sred[tid][0], y1 = sred[tid][1];
        y0.x += x0.x; y0.y += x0.y; y0.z += x0.z; y0.w += x0.w;
        y1.x += x1.x; y1.y += x1.y; y1.z += x1.z; y1.w += x1.w;
        __nv_bfloat162 p0 = __floats2bfloat162_rn(y0.x, y0.y);
        __nv_bfloat162 p1 = __floats2bfloat162_rn(y0.z, y0.w);
        __nv_bfloat162 p2 = __floats2bfloat162_rn(y1.x, y1.y);
        __nv_bfloat162 p3 = __floats2bfloat162_rn(y1.z, y1.w);
        uint4 pk;
        pk.x = *(uint32_t*)&p0; pk.y = *(uint32_t*)&p1;
        pk.z = *(uint32_t*)&p2; pk.w = *(uint32_t*)&p3;
        *(uint4*)(g_aggh + (size_t)n * CH + tid * 8) = pk;
    }
}

// ---------------- block reduction helper ----------------
__device__ __forceinline__ float blocksum256(float v, float* sh) {
    #pragma unroll
    for (int o = 16; o > 0; o >>= 1) v += __shfl_xor_sync(0xffffffffu, v, o);
    if ((threadIdx.x & 31) == 0) sh[threadIdx.x >> 5] = v;
    __syncthreads();
    float s = 0.f;
    #pragma unroll
    for (int i = 0; i < 8; i++) s += sh[i];
    __syncthreads();
    return s;
}

// ---------------- slots assembly + residual + LN1 ----------------
__global__ __launch_bounds__(256) void ln1_kernel(
    const float* __restrict__ query, const float* __restrict__ b_out,
    const float* __restrict__ gamma, const float* __restrict__ beta)
{
    __shared__ float sh[8];
    const int n = blockIdx.x, c = threadIdx.x;
    float m = g_cnt[n];
    float q = query[(size_t)n * CH + c];
    float s = m * (q + b_out[c]) + g_proj[(size_t)n * CH + c];
    float t = s / fmaxf(m, 1.0f) + q;
    float mu = blocksum256(t, sh) * (1.0f / CH);
    float d = t - mu;
    float var = blocksum256(d * d, sh) * (1.0f / CH);
    float xv = d * rsqrtf(var + 1e-5f) * gamma[c] + beta[c];
    g_x[(size_t)n * CH + c] = xv;
    g_x_h[(size_t)n * CH + c] = __float2bfloat16_rn(xv);
}

// ---------------- FFN residual + LN2 -> output ----------------
__global__ __launch_bounds__(256) void ln2_kernel(
    const float* __restrict__ gamma, const float* __restrict__ beta,
    float* __restrict__ out)
{
    __shared__ float sh[8];
    const int n = blockIdx.x, c = threadIdx.x;
    float t = g_x[(size_t)n * CH + c] + g_ffn2[(size_t)n * CH + c];
    float mu = blocksum256(t, sh) * (1.0f / CH);
    float d = t - mu;
    float var = blocksum256(d * d, sh) * (1.0f / CH);
    out[(size_t)n * CH + c] = d * rsqrtf(var + 1e-5f) * gamma[c] + beta[c];
}

// ---------------- host launcher ----------------
extern "C" void kernel_launch(void* const* d_in, const int* in_sizes, int n_in,
                              void* d_out, int out_size) {
    const float* query   = (const float*)d_in[0];
    const float* value   = (const float*)d_in[2];
    const float* refpts  = (const float*)d_in[3];
    const int*   bev     = (const int*)d_in[6];
    const float* W_value = (const float*)d_in[7];
    const float* b_value = (const float*)d_in[8];
    const float* W_off   = (const float*)d_in[9];
    const float* b_off   = (const float*)d_in[10];
    const float* W_attn  = (const float*)d_in[11];
    const float* b_attn  = (const float*)d_in[12];
    const float* W_out   = (const float*)d_in[13];
    const float* b_out   = (const float*)d_in[14];
    const float* ln1_g   = (const float*)d_in[15];
    const float* ln1_b   = (const float*)d_in[16];
    const float* W1      = (const float*)d_in[17];
    const float* b1      = (const float*)d_in[18];
    const float* W2      = (const float*)d_in[19];
    const float* b2      = (const float*)d_in[20];
    const float* ln2_g   = (const float*)d_in[21];
    const float* ln2_b   = (const float*)d_in[22];
    float* out = (float*)d_out;

    void *p_valh, *p_Wvalh, *p_vproj, *p_qh, *p_Wfh, *p_bf, *p_Wouth, *p_W1h, *p_W2h;
    void *p_fused, *p_aggh, *p_proj, *p_xh, *p_ffn1h, *p_ffn2;
    cudaGetSymbolAddress(&p_valh,   g_val_h);
    cudaGetSymbolAddress(&p_Wvalh,  g_Wval_h);
    cudaGetSymbolAddress(&p_vproj,  g_vproj);
    cudaGetSymbolAddress(&p_qh,     g_q_h);
    cudaGetSymbolAddress(&p_Wfh,    g_Wf_h);
    cudaGetSymbolAddress(&p_bf,     g_bf);
    cudaGetSymbolAddress(&p_Wouth,  g_Wout_h);
    cudaGetSymbolAddress(&p_W1h,    g_W1_h);
    cudaGetSymbolAddress(&p_W2h,    g_W2_h);
    cudaGetSymbolAddress(&p_fused,  g_fused);
    cudaGetSymbolAddress(&p_aggh,   g_aggh);
    cudaGetSymbolAddress(&p_proj,   g_proj);
    cudaGetSymbolAddress(&p_xh,     g_x_h);
    cudaGetSymbolAddress(&p_ffn1h,  g_ffn1h);
    cudaGetSymbolAddress(&p_ffn2,   g_ffn2);

    static cudaStream_t s2 = nullptr;
    static cudaEvent_t ev_fork = nullptr, ev_join = nullptr;
    if (s2 == nullptr) {
        cudaStreamCreateWithFlags(&s2, cudaStreamNonBlocking);
        cudaEventCreateWithFlags(&ev_fork, cudaEventDisableTiming);
        cudaEventCreateWithFlags(&ev_join, cudaEventDisableTiming);
    }

    // ---- fork: value/W_value conversion + vproj GEMM on s2 ----
    cudaEventRecord(ev_fork, 0);
    cudaStreamWaitEvent(s2, ev_fork, 0);
    {
        int nconv = (MVAL * CH / 4 + CH * CH / 4 + 255) / 256;
        conv_val_kernel<<<nconv, 256, 0, s2>>>(value, W_value);
        hgemm_bf16<1, __nv_bfloat16><<<dim3(MPAD / 128, CH / 64), 256, 0, s2>>>(
            (const __nv_bfloat16*)p_valh, (const __nv_bfloat16*)p_Wvalh,
            b_value, (__nv_bfloat16*)p_vproj, MPAD, CH, CH);
    }
    cudaEventRecord(ev_join, s2);

    // ---- main stream: prep + fused off/attn GEMM ----
    prep_kernel<<<2585, 256>>>(bev, query, W_off, W_attn, b_off, b_attn,
                               W_out, W1, W2);
    hgemm_bf16<1, float><<<dim3(NQ / 128, NFUS / 64), 256>>>(
        (const __nv_bfloat16*)p_qh, (const __nv_bfloat16*)p_Wfh,
        (const float*)p_bf, (float*)p_fused, NQ, NFUS, CH);

    // ---- join, then sampling ----
    cudaStreamWaitEvent(0, ev_join, 0);
    sample_kernel<<<NQ, 256>>>(refpts);

    // output projection: agg(bf16) @ W_out (bias folded into ln1)
    hgemm_bf16<0, float><<<dim3(NQ / 128, CH / 64), 256>>>(
        (const __nv_bfloat16*)p_aggh, (const __nv_bfloat16*)p_Wouth,
        nullptr, (float*)p_proj, NQ, CH, CH);

    // slots + residual + LN1
    ln1_kernel<<<NQ, 256>>>(query, b_out, ln1_g, ln1_b);

    // FFN up: relu(x @ W1 + b1) -> bf16
    hgemm_bf16<2, __nv_bfloat16><<<dim3(NQ / 128, DFFN / 64), 256>>>(
        (const __nv_bfloat16*)p_xh, (const __nv_bfloat16*)p_W1h,
        b1, (__nv_bfloat16*)p_ffn1h, NQ, DFFN, CH);

    // FFN down: ffn1(bf16) @ W2 + b2
    hgemm_bf16<1, float><<<dim3(NQ / 128, CH / 64), 256>>>(
        (const __nv_bfloat16*)p_ffn1h, (const __nv_bfloat16*)p_W2h,
        b2, (float*)p_ffn2, NQ, CH, DFFN);

    // residual + LN2 -> out
    ln2_kernel<<<NQ, 256>>>(ln2_g, ln2_b, out);

    (void)in_sizes; (void)n_in; (void)out_size;
}